// round 4
// baseline (speedup 1.0000x reference)
#include <cuda_runtime.h>
#include <stdint.h>

#define N_NODES 50000
#define N_EDGES 800000
#define D 256

// ---------------- device scratch (no dynamic allocation allowed) ----------------
__device__ float g_src[(size_t)N_NODES * D];   // SRC = x@W_src + b_src  (51.2 MB, L2-resident)
__device__ int   g_deg[N_NODES];
__device__ int   g_rowptr[N_NODES + 1];
__device__ int   g_cursor[N_NODES];
__device__ int   g_esrc[N_EDGES];              // CSR payload: source node per incoming edge
__device__ int   g_is64;                        // 1 if edge_index is int64, 0 if int32

// ---------------- K0: detect edge_index dtype on device ----------------
// int64 data (values < 2^31) viewed as int32 has zero high words at odd slots.
__global__ void k_detect(const int* __restrict__ ei32) {
    if (threadIdx.x == 0 && blockIdx.x == 0) {
        int nz = 0;
        #pragma unroll 8
        for (int i = 0; i < 128; i++) nz |= ei32[2 * i + 1];
        g_is64 = (nz == 0) ? 1 : 0;
    }
}

__device__ __forceinline__ int load_idx(const void* ei, int is64, int pos) {
    if (is64) return (int)((const long long*)ei)[pos];
    return ((const int*)ei)[pos];
}

// ---------------- K1: zero degree histogram ----------------
__global__ void k_zero_deg() {
    int i = blockIdx.x * blockDim.x + threadIdx.x;
    if (i < N_NODES) g_deg[i] = 0;
}

// ---------------- K2: degree histogram over destination (col) ----------------
__global__ void k_hist(const void* __restrict__ ei) {
    int e = blockIdx.x * blockDim.x + threadIdx.x;
    if (e < N_EDGES) {
        int col = load_idx(ei, g_is64, N_EDGES + e);
        if ((unsigned)col < (unsigned)N_NODES)
            atomicAdd(&g_deg[col], 1);
    }
}

// ---------------- K3: single-block exclusive scan -> rowptr, cursor ----------------
__global__ void k_scan() {
    __shared__ int sums[1024];
    const int CH = (N_NODES + 1023) / 1024;  // 49
    int t = threadIdx.x;
    int base = t * CH;

    int s = 0;
    #pragma unroll 4
    for (int i = 0; i < CH; i++) {
        int idx = base + i;
        if (idx < N_NODES) s += g_deg[idx];
    }
    sums[t] = s;
    __syncthreads();

    // Hillis-Steele inclusive scan over the 1024 chunk sums
    for (int off = 1; off < 1024; off <<= 1) {
        int v = (t >= off) ? sums[t - off] : 0;
        __syncthreads();
        sums[t] += v;
        __syncthreads();
    }
    int run = (t == 0) ? 0 : sums[t - 1];

    for (int i = 0; i < CH; i++) {
        int idx = base + i;
        if (idx < N_NODES) {
            g_rowptr[idx] = run;
            g_cursor[idx] = run;
            run += g_deg[idx];
        }
    }
    if (t == 1023) g_rowptr[N_NODES] = run;   // = total edge count
}

// ---------------- K4: counting-sort fill of CSR buckets ----------------
__global__ void k_fill(const void* __restrict__ ei) {
    int e = blockIdx.x * blockDim.x + threadIdx.x;
    if (e < N_EDGES) {
        int is64 = g_is64;
        int row = load_idx(ei, is64, e);
        int col = load_idx(ei, is64, N_EDGES + e);
        if ((unsigned)row < (unsigned)N_NODES && (unsigned)col < (unsigned)N_NODES) {
            int pos = atomicAdd(&g_cursor[col], 1);
            if ((unsigned)pos < (unsigned)N_EDGES) g_esrc[pos] = row;
        }
    }
}

// ---------------- K5: fused triple GEMM ----------------
// SRC            = x @ W_src  + b_src                        -> g_src
// d_out (OUT0)   = x @ W_self + b_self - deg*(x@W_dst+b_dst) -> d_out
// 64x64 block tile, BK=16, 256 threads, 4x4 micro-tile, 3 accumulator sets.
#define BM 64
#define BN 64
#define BK 16

__global__ __launch_bounds__(256)
void k_gemm(const float* __restrict__ x,
            const float* __restrict__ Wsrc, const float* __restrict__ bsrc,
            const float* __restrict__ Wdst, const float* __restrict__ bdst,
            const float* __restrict__ Wself, const float* __restrict__ bself,
            float* __restrict__ out) {
    __shared__ __align__(16) float As[BK][BM];
    __shared__ __align__(16) float Bs[3][BK][BN];

    const int tid = threadIdx.x;
    const int tx = tid & 15;     // 0..15 -> 4 output columns each
    const int ty = tid >> 4;     // 0..15 -> 4 output rows each

    const int rowBase = blockIdx.y * BM;
    const int n0 = blockIdx.x * BN;

    // A-load mapping: each thread loads one float4 along K
    const int aRow = tid >> 2;          // 0..63
    const int aK4  = (tid & 3) * 4;     // 0,4,8,12
    // B-load mapping: each thread loads one float4 per matrix
    const int bK   = tid >> 4;          // 0..15
    const int bJ4  = (tid & 15) * 4;    // 0..60

    const float* Ws[3] = {Wsrc, Wdst, Wself};

    float acc_s[4][4] = {};
    float acc_d[4][4] = {};
    float acc_f[4][4] = {};

    for (int k0 = 0; k0 < D; k0 += BK) {
        // load A tile (x), transposed into As[k][m]
        float4 av = make_float4(0.f, 0.f, 0.f, 0.f);
        int gr = rowBase + aRow;
        if (gr < N_NODES)
            av = *reinterpret_cast<const float4*>(&x[(size_t)gr * D + k0 + aK4]);
        As[aK4 + 0][aRow] = av.x;
        As[aK4 + 1][aRow] = av.y;
        As[aK4 + 2][aRow] = av.z;
        As[aK4 + 3][aRow] = av.w;

        // load the three B tiles
        #pragma unroll
        for (int m = 0; m < 3; m++) {
            float4 bv = *reinterpret_cast<const float4*>(&Ws[m][(size_t)(k0 + bK) * D + n0 + bJ4]);
            *reinterpret_cast<float4*>(&Bs[m][bK][bJ4]) = bv;
        }
        __syncthreads();

        #pragma unroll
        for (int kk = 0; kk < BK; kk++) {
            float4 a  = *reinterpret_cast<const float4*>(&As[kk][ty * 4]);
            float4 b0 = *reinterpret_cast<const float4*>(&Bs[0][kk][tx * 4]);
            float4 b1 = *reinterpret_cast<const float4*>(&Bs[1][kk][tx * 4]);
            float4 b2 = *reinterpret_cast<const float4*>(&Bs[2][kk][tx * 4]);
            const float ar[4] = {a.x, a.y, a.z, a.w};
            const float bs0[4] = {b0.x, b0.y, b0.z, b0.w};
            const float bs1[4] = {b1.x, b1.y, b1.z, b1.w};
            const float bs2[4] = {b2.x, b2.y, b2.z, b2.w};
            #pragma unroll
            for (int i = 0; i < 4; i++) {
                #pragma unroll
                for (int j = 0; j < 4; j++) {
                    acc_s[i][j] = fmaf(ar[i], bs0[j], acc_s[i][j]);
                    acc_d[i][j] = fmaf(ar[i], bs1[j], acc_d[i][j]);
                    acc_f[i][j] = fmaf(ar[i], bs2[j], acc_f[i][j]);
                }
            }
        }
        __syncthreads();
    }

    // epilogue
    const int c0 = n0 + tx * 4;
    const float4 bsrc4  = *reinterpret_cast<const float4*>(&bsrc[c0]);
    const float4 bdst4  = *reinterpret_cast<const float4*>(&bdst[c0]);
    const float4 bself4 = *reinterpret_cast<const float4*>(&bself[c0]);
    const float bsr[4] = {bsrc4.x, bsrc4.y, bsrc4.z, bsrc4.w};
    const float bds[4] = {bdst4.x, bdst4.y, bdst4.z, bdst4.w};
    const float bsf[4] = {bself4.x, bself4.y, bself4.z, bself4.w};

    #pragma unroll
    for (int i = 0; i < 4; i++) {
        int v = rowBase + ty * 4 + i;
        if (v >= N_NODES) break;
        float degf = (float)(g_rowptr[v + 1] - g_rowptr[v]);
        float4 so, oo;
        float* sp = (float*)&so;
        float* op = (float*)&oo;
        #pragma unroll
        for (int j = 0; j < 4; j++) {
            float sv = acc_s[i][j] + bsr[j];
            sp[j] = sv;
            op[j] = acc_f[i][j] + bsf[j] - degf * (acc_d[i][j] + bds[j]);
        }
        *reinterpret_cast<float4*>(&g_src[(size_t)v * D + c0]) = so;
        *reinterpret_cast<float4*>(&out[(size_t)v * D + c0]) = oo;
    }
}

// ---------------- K6: per-node gather reduce: out[v] += sum_{nbr} SRC[nbr] ----------------
__global__ __launch_bounds__(256)
void k_reduce(float* __restrict__ out) {
    const int v = blockIdx.x;
    const int dim = threadIdx.x;       // 256 dims, one per thread
    const int s = g_rowptr[v];
    const int e = g_rowptr[v + 1];

    __shared__ int nbr[512];

    float acc = 0.f;
    for (int base = s; base < e; base += 512) {
        int cnt = min(512, e - base);
        for (int i = threadIdx.x; i < cnt; i += 256) nbr[i] = g_esrc[base + i];
        __syncthreads();
        int i = 0;
        for (; i + 4 <= cnt; i += 4) {
            float x0 = g_src[(size_t)nbr[i + 0] * D + dim];
            float x1 = g_src[(size_t)nbr[i + 1] * D + dim];
            float x2 = g_src[(size_t)nbr[i + 2] * D + dim];
            float x3 = g_src[(size_t)nbr[i + 3] * D + dim];
            acc += (x0 + x1) + (x2 + x3);
        }
        for (; i < cnt; i++) acc += g_src[(size_t)nbr[i] * D + dim];
        __syncthreads();
    }
    if (e > s) out[(size_t)v * D + dim] += acc;
}

// ---------------- launch ----------------
extern "C" void kernel_launch(void* const* d_in, const int* in_sizes, int n_in,
                              void* d_out, int out_size) {
    const float* x     = (const float*)d_in[0];
    const void*  ei    = d_in[1];
    const float* Wsrc  = (const float*)d_in[2];
    const float* bsrc  = (const float*)d_in[3];
    const float* Wdst  = (const float*)d_in[4];
    const float* bdst  = (const float*)d_in[5];
    const float* Wself = (const float*)d_in[6];
    const float* bself = (const float*)d_in[7];
    float* out = (float*)d_out;

    k_detect<<<1, 32>>>((const int*)ei);
    k_zero_deg<<<(N_NODES + 255) / 256, 256>>>();
    k_hist<<<(N_EDGES + 255) / 256, 256>>>(ei);
    k_scan<<<1, 1024>>>();
    k_fill<<<(N_EDGES + 255) / 256, 256>>>(ei);

    dim3 ggrid(D / BN, (N_NODES + BM - 1) / BM);  // (4, 782)
    k_gemm<<<ggrid, 256>>>(x, Wsrc, bsrc, Wdst, bdst, Wself, bself, out);

    k_reduce<<<N_NODES, 256>>>(out);
}

// round 6
// speedup vs baseline: 1.5942x; 1.5942x over previous
#include <cuda_runtime.h>
#include <cuda_bf16.h>
#include <stdint.h>

#define N_NODES 50000
#define N_EDGES 800000
#define D 256

// ================= device scratch (no dynamic allocation allowed) =================
__device__ float g_src[(size_t)N_NODES * D];   // SRC = x@W_src + b_src (51.2 MB)
__device__ int   g_deg[N_NODES];
__device__ int   g_rowptr[N_NODES + 1];
__device__ int   g_cursor[N_NODES];
__device__ int   g_esrc[N_EDGES];
__device__ int   g_is64;
__device__ int   g_bsum[256];
__device__ int   g_boff[256];
// pre-transposed, pre-split, pre-swizzled weights:
// block id = ((mat*2+split)*4 + ntile)*4 + kchunk, each block 8192 bytes (64n x 64k bf16, SW128)
__device__ __align__(256) unsigned char g_wt[3 * 2 * 4 * 4 * 8192];

__device__ __forceinline__ uint32_t smem_u32(const void* p) {
    uint32_t a;
    asm("{ .reg .u64 t; cvta.to.shared.u64 t, %1; cvt.u32.u64 %0, t; }" : "=r"(a) : "l"(p));
    return a;
}
__device__ __forceinline__ uint32_t swz(uint32_t off) { return off ^ ((off >> 3) & 0x70); }

// ldmatrix x4 (non-transposed, b16)
#define LDSM_X4(r0, r1, r2, r3, addr) \
    asm volatile("ldmatrix.sync.aligned.m8n8.x4.shared.b16 {%0,%1,%2,%3}, [%4];" \
        : "=r"(r0), "=r"(r1), "=r"(r2), "=r"(r3) : "r"(addr))

// mma m16n8k16 bf16 -> f32
#define MMA_BF16(c, a, b0v, b1v) \
    asm volatile("mma.sync.aligned.m16n8k16.row.col.f32.bf16.bf16.f32 " \
        "{%0,%1,%2,%3}, {%4,%5,%6,%7}, {%8,%9}, {%0,%1,%2,%3};" \
        : "+f"((c)[0]), "+f"((c)[1]), "+f"((c)[2]), "+f"((c)[3]) \
        : "r"((a)[0]), "r"((a)[1]), "r"((a)[2]), "r"((a)[3]), "r"(b0v), "r"(b1v))

// ================= K0: dtype detect =================
__global__ void k_detect(const int* __restrict__ ei32) {
    if (threadIdx.x == 0 && blockIdx.x == 0) {
        int nz = 0;
        #pragma unroll 8
        for (int i = 0; i < 128; i++) nz |= ei32[2 * i + 1];
        g_is64 = (nz == 0) ? 1 : 0;
    }
}
__device__ __forceinline__ int load_idx(const void* ei, int is64, int pos) {
    if (is64) return (int)((const long long*)ei)[pos];
    return ((const int*)ei)[pos];
}

// ================= degree / CSR build =================
__global__ void k_zero_deg() {
    int i = blockIdx.x * blockDim.x + threadIdx.x;
    if (i < N_NODES) g_deg[i] = 0;
}
__global__ void k_hist(const void* __restrict__ ei) {
    int e = blockIdx.x * blockDim.x + threadIdx.x;
    if (e < N_EDGES) {
        int col = load_idx(ei, g_is64, N_EDGES + e);
        if ((unsigned)col < (unsigned)N_NODES) atomicAdd(&g_deg[col], 1);
    }
}
__global__ void k_scan1() {
    __shared__ int sh[256];
    int i = blockIdx.x * 256 + threadIdx.x;
    int v = (i < N_NODES) ? g_deg[i] : 0;
    sh[threadIdx.x] = v; __syncthreads();
    for (int off = 128; off > 0; off >>= 1) {
        if (threadIdx.x < off) sh[threadIdx.x] += sh[threadIdx.x + off];
        __syncthreads();
    }
    if (threadIdx.x == 0) g_bsum[blockIdx.x] = sh[0];
}
__global__ void k_scan2(int nblk) {
    __shared__ int sh[256];
    int t = threadIdx.x;
    int v = (t < nblk) ? g_bsum[t] : 0;
    sh[t] = v; __syncthreads();
    for (int off = 1; off < 256; off <<= 1) {
        int u = (t >= off) ? sh[t - off] : 0;
        __syncthreads(); sh[t] += u; __syncthreads();
    }
    g_boff[t] = sh[t] - v;
    if (t == 255) g_rowptr[N_NODES] = sh[255];
}
__global__ void k_scan3() {
    __shared__ int sh[256];
    int t = threadIdx.x;
    int i = blockIdx.x * 256 + t;
    int v = (i < N_NODES) ? g_deg[i] : 0;
    sh[t] = v; __syncthreads();
    for (int off = 1; off < 256; off <<= 1) {
        int u = (t >= off) ? sh[t - off] : 0;
        __syncthreads(); sh[t] += u; __syncthreads();
    }
    if (i < N_NODES) {
        int excl = sh[t] - v + g_boff[blockIdx.x];
        g_rowptr[i] = excl;
        g_cursor[i] = excl;
    }
}
__global__ void k_fill(const void* __restrict__ ei) {
    int e = blockIdx.x * blockDim.x + threadIdx.x;
    if (e < N_EDGES) {
        int is64 = g_is64;
        int row = load_idx(ei, is64, e);
        int col = load_idx(ei, is64, N_EDGES + e);
        if ((unsigned)row < (unsigned)N_NODES && (unsigned)col < (unsigned)N_NODES) {
            int pos = atomicAdd(&g_cursor[col], 1);
            if ((unsigned)pos < (unsigned)N_EDGES) g_esrc[pos] = row;
        }
    }
}

// ================= K-prep: transpose + bf16-split + swizzle weights =================
__global__ void k_prep(const float* __restrict__ Wsrc,
                       const float* __restrict__ Wdst,
                       const float* __restrict__ Wself) {
    int idx = blockIdx.x * blockDim.x + threadIdx.x;
    if (idx >= 3 * D * D) return;
    int m = idx >> 16;
    int rem = idx & 65535;
    int k = rem >> 8;       // input dim
    int n = rem & 255;      // output dim
    const float* W = (m == 0) ? Wsrc : (m == 1) ? Wdst : Wself;
    float w = W[k * D + n];
    __nv_bfloat16 hi = __float2bfloat16(w);
    __nv_bfloat16 lo = __float2bfloat16(w - __bfloat162float(hi));
    int ntile = n >> 6, r = n & 63;
    int kc = k >> 6, kl = k & 63;
    uint32_t off = swz((uint32_t)(r * 128 + kl * 2));
    size_t blk_hi = (size_t)(((m * 2 + 0) * 4 + ntile) * 4 + kc) * 8192;
    size_t blk_lo = (size_t)(((m * 2 + 1) * 4 + ntile) * 4 + kc) * 8192;
    *(__nv_bfloat16*)(g_wt + blk_hi + off) = hi;
    *(__nv_bfloat16*)(g_wt + blk_lo + off) = lo;
}

// ================= split-bf16 mma.sync fused triple GEMM =================
// CTA: M=128, N=64, 3 matrices. 8 warps in 4(m) x 2(n). Warp: 32x32 per matrix.
// K = 256 in 4 chunks of 64. acc = Ahi*Bhi + Ahi*Blo + Alo*Bhi (fp32).
#define SMEM_A_OFF   1024
#define SMEM_B_OFF   (1024 + 32768)
#define SMEM_TOTAL_G (1024 + 32768 + 49152)

__global__ __launch_bounds__(256, 1)
void k_gemm_mma(const float* __restrict__ x,
                const float* __restrict__ bsrc,
                const float* __restrict__ bdst,
                const float* __restrict__ bself,
                float* __restrict__ out) {
    extern __shared__ __align__(1024) char smem[];
    const uint32_t sbase = smem_u32(smem);
    const int tid = threadIdx.x;
    const int wid = tid >> 5;
    const int lid = tid & 31;
    const int m0 = blockIdx.y * 128;
    const int n0 = blockIdx.x * 64;
    const int wm = wid & 3;    // m block of 32
    const int wn = wid >> 2;   // n block of 32

    float* sb = (float*)(smem + 64);   // 192 bias floats
    if (tid < 64)       sb[tid] = bsrc[n0 + tid];
    else if (tid < 128) sb[tid] = bdst[n0 + tid - 64];
    else if (tid < 192) sb[tid] = bself[n0 + tid - 128];

    // per-lane ldmatrix row components
    const int a_row = wm * 32 + (lid & 15);          // + mt*16
    const int a_kh  = (lid >> 4) << 4;               // 0 or 16 bytes (k half)
    const int b_row = wn * 32 + (lid & 7) + ((lid >> 4) << 3);  // + np*16
    const int b_kh  = ((lid >> 3) & 1) << 4;         // 0 or 16 bytes

    float acc[3][2][4][4];
    #pragma unroll
    for (int m = 0; m < 3; m++)
        #pragma unroll
        for (int i = 0; i < 2; i++)
            #pragma unroll
            for (int j = 0; j < 4; j++)
                #pragma unroll
                for (int q = 0; q < 4; q++) acc[m][i][j][q] = 0.f;

    for (int c = 0; c < 4; c++) {
        __syncthreads();
        char* Ahi = smem + SMEM_A_OFF;
        char* Alo = Ahi + 16384;
        char* Bb  = smem + SMEM_B_OFF;
        const int kbase = c * 64;

        // ---- A tile: load x f32, split to bf16 hi/lo, store swizzled (128 rows x 128B) ----
        #pragma unroll
        for (int it = 0; it < 4; it++) {
            int u = tid + it * 256;            // 0..1023 16B-units
            int r = u >> 3, j = u & 7;
            int row = m0 + r;
            union { __nv_bfloat16 h[8]; uint4 u4; } H, L;
            H.u4 = make_uint4(0, 0, 0, 0); L.u4 = make_uint4(0, 0, 0, 0);
            if (row < N_NODES) {
                const float4* p = (const float4*)(x + (size_t)row * D + kbase + j * 8);
                float4 a = p[0], b = p[1];
                float f[8] = {a.x, a.y, a.z, a.w, b.x, b.y, b.z, b.w};
                #pragma unroll
                for (int q = 0; q < 8; q++) {
                    __nv_bfloat16 h = __float2bfloat16(f[q]);
                    H.h[q] = h;
                    L.h[q] = __float2bfloat16(f[q] - __bfloat162float(h));
                }
            }
            uint32_t sw = swz((uint32_t)(r * 128 + j * 16));
            *(uint4*)(Ahi + sw) = H.u4;
            *(uint4*)(Alo + sw) = L.u4;
        }

        // ---- B tiles: verbatim copy of pre-swizzled blocks ----
        #pragma unroll
        for (int it = 0; it < 12; it++) {
            int t = tid + it * 256;            // 0..3071
            int op = t >> 9;                   // mat*2+split
            int w  = t & 511;
            const uint4* src = (const uint4*)(g_wt + (size_t)((op * 4 + blockIdx.x) * 4 + c) * 8192) + w;
            *((uint4*)(Bb + op * 8192) + w) = *src;
        }
        __syncthreads();

        // ---- compute: 4 k16 steps ----
        #pragma unroll
        for (int kk = 0; kk < 4; kk++) {
            const int kb = kk * 32;            // byte offset of this k16 within 128B row

            // A fragments: [split][mt][4]
            uint32_t af[2][2][4];
            #pragma unroll
            for (int mt = 0; mt < 2; mt++) {
                uint32_t off = swz((uint32_t)((a_row + mt * 16) * 128 + kb + a_kh));
                LDSM_X4(af[0][mt][0], af[0][mt][1], af[0][mt][2], af[0][mt][3],
                        sbase + SMEM_A_OFF + off);
                LDSM_X4(af[1][mt][0], af[1][mt][1], af[1][mt][2], af[1][mt][3],
                        sbase + SMEM_A_OFF + 16384 + off);
            }

            #pragma unroll
            for (int mat = 0; mat < 3; mat++) {
                // B fragments: [split][nt][2] ; ldmatrix x4 covers 2 n-tiles
                uint32_t bf[2][4][2];
                #pragma unroll
                for (int sp = 0; sp < 2; sp++) {
                    uint32_t bb = sbase + SMEM_B_OFF + (uint32_t)(mat * 2 + sp) * 8192;
                    #pragma unroll
                    for (int np = 0; np < 2; np++) {
                        uint32_t off = swz((uint32_t)((b_row + np * 16) * 128 + kb + b_kh));
                        LDSM_X4(bf[sp][np * 2][0], bf[sp][np * 2][1],
                                bf[sp][np * 2 + 1][0], bf[sp][np * 2 + 1][1],
                                bb + off);
                    }
                }
                #pragma unroll
                for (int mt = 0; mt < 2; mt++) {
                    #pragma unroll
                    for (int nt = 0; nt < 4; nt++) {
                        MMA_BF16(acc[mat][mt][nt], af[0][mt], bf[0][nt][0], bf[0][nt][1]); // hi*hi
                        MMA_BF16(acc[mat][mt][nt], af[0][mt], bf[1][nt][0], bf[1][nt][1]); // hi*lo
                        MMA_BF16(acc[mat][mt][nt], af[1][mt], bf[0][nt][0], bf[0][nt][1]); // lo*hi
                    }
                }
            }
        }
    }

    // ---- epilogue ----
    const int qr = lid >> 2;          // 0..7
    const int qc = (lid & 3) * 2;     // 0,2,4,6
    #pragma unroll
    for (int mt = 0; mt < 2; mt++) {
        #pragma unroll
        for (int half = 0; half < 2; half++) {
            int row = m0 + wm * 32 + mt * 16 + qr + half * 8;
            if (row >= N_NODES) continue;
            float degf = (float)g_deg[row];
            #pragma unroll
            for (int nt = 0; nt < 4; nt++) {
                int cl = wn * 32 + nt * 8 + qc;    // 0..63 local col
                float s0 = acc[0][mt][nt][half * 2 + 0] + sb[cl + 0];
                float s1 = acc[0][mt][nt][half * 2 + 1] + sb[cl + 1];
                float o0 = acc[2][mt][nt][half * 2 + 0] + sb[128 + cl + 0]
                         - degf * (acc[1][mt][nt][half * 2 + 0] + sb[64 + cl + 0]);
                float o1 = acc[2][mt][nt][half * 2 + 1] + sb[128 + cl + 1]
                         - degf * (acc[1][mt][nt][half * 2 + 1] + sb[64 + cl + 1]);
                *(float2*)&g_src[(size_t)row * D + n0 + cl] = make_float2(s0, s1);
                *(float2*)&out[(size_t)row * D + n0 + cl]   = make_float2(o0, o1);
            }
        }
    }
}

// ================= K6: gather reduce: out[v] += sum_{nbr} SRC[nbr] =================
__global__ __launch_bounds__(256)
void k_reduce(float* __restrict__ out) {
    const int v = blockIdx.x;
    const int dim = threadIdx.x;
    const int s = g_rowptr[v];
    const int e = g_rowptr[v + 1];

    __shared__ int nbr[512];

    float acc = 0.f;
    for (int base = s; base < e; base += 512) {
        int cnt = min(512, e - base);
        for (int i = threadIdx.x; i < cnt; i += 256) nbr[i] = g_esrc[base + i];
        __syncthreads();
        int i = 0;
        for (; i + 4 <= cnt; i += 4) {
            float x0 = g_src[(size_t)nbr[i + 0] * D + dim];
            float x1 = g_src[(size_t)nbr[i + 1] * D + dim];
            float x2 = g_src[(size_t)nbr[i + 2] * D + dim];
            float x3 = g_src[(size_t)nbr[i + 3] * D + dim];
            acc += (x0 + x1) + (x2 + x3);
        }
        for (; i < cnt; i++) acc += g_src[(size_t)nbr[i] * D + dim];
        __syncthreads();
    }
    if (e > s) out[(size_t)v * D + dim] += acc;
}

// ================= launch =================
extern "C" void kernel_launch(void* const* d_in, const int* in_sizes, int n_in,
                              void* d_out, int out_size) {
    const float* x     = (const float*)d_in[0];
    const void*  ei    = d_in[1];
    const float* Wsrc  = (const float*)d_in[2];
    const float* bsrc  = (const float*)d_in[3];
    const float* Wdst  = (const float*)d_in[4];
    const float* bdst  = (const float*)d_in[5];
    const float* Wself = (const float*)d_in[6];
    const float* bself = (const float*)d_in[7];
    float* out = (float*)d_out;

    const int NB = (N_NODES + 255) / 256;      // 196

    k_detect<<<1, 32>>>((const int*)ei);
    k_zero_deg<<<NB, 256>>>();
    k_hist<<<(N_EDGES + 255) / 256, 256>>>(ei);
    k_scan1<<<NB, 256>>>();
    k_scan2<<<1, 256>>>(NB);
    k_scan3<<<NB, 256>>>();
    k_fill<<<(N_EDGES + 255) / 256, 256>>>(ei);
    k_prep<<<(3 * D * D + 255) / 256, 256>>>(Wsrc, Wdst, Wself);

    cudaFuncSetAttribute(k_gemm_mma, cudaFuncAttributeMaxDynamicSharedMemorySize, SMEM_TOTAL_G);
    dim3 ggrid(4, (N_NODES + 127) / 128);      // (4, 391)
    k_gemm_mma<<<ggrid, 256, SMEM_TOTAL_G>>>(x, bsrc, bdst, bself, out);

    k_reduce<<<N_NODES, 256>>>(out);
}

// round 7
// speedup vs baseline: 2.0109x; 1.2614x over previous
#include <cuda_runtime.h>
#include <cuda_bf16.h>
#include <stdint.h>

#define N_NODES 50000
#define N_EDGES 800000
#define D 256
#define MTILES 391           // ceil(50000/128)

// ================= device scratch (no dynamic allocation allowed) =================
__device__ float g_src[(size_t)N_NODES * D];   // SRC = x@W_src + b_src (51.2 MB)
__device__ int   g_deg[N_NODES];
__device__ int   g_rowptr[N_NODES + 1];
__device__ int   g_cursor[N_NODES];
__device__ int   g_esrc[N_EDGES];
__device__ int   g_is64;
__device__ int   g_bsum[256];
__device__ int   g_boff[256];
// pre-transposed, pre-split, pre-swizzled weights:
// block id = ((mat*2+split)*4 + ntile)*4 + kchunk, each 8192 B (64n x 64k bf16, SW128)
__device__ __align__(256) unsigned char g_wt[3 * 2 * 4 * 4 * 8192];
// pre-split, pre-swizzled activations: block id = mtile*4 + kchunk, each 16384 B (128m x 64k bf16, SW128)
__device__ __align__(256) unsigned char g_xhi[(size_t)MTILES * 4 * 16384];
__device__ __align__(256) unsigned char g_xlo[(size_t)MTILES * 4 * 16384];

__device__ __forceinline__ uint32_t smem_u32(const void* p) {
    uint32_t a;
    asm("{ .reg .u64 t; cvta.to.shared.u64 t, %1; cvt.u32.u64 %0, t; }" : "=r"(a) : "l"(p));
    return a;
}
__device__ __forceinline__ uint32_t swz(uint32_t off) { return off ^ ((off >> 3) & 0x70); }

#define LDSM_X4(r0, r1, r2, r3, addr) \
    asm volatile("ldmatrix.sync.aligned.m8n8.x4.shared.b16 {%0,%1,%2,%3}, [%4];" \
        : "=r"(r0), "=r"(r1), "=r"(r2), "=r"(r3) : "r"(addr))

#define MMA_BF16(c, a, b0v, b1v) \
    asm volatile("mma.sync.aligned.m16n8k16.row.col.f32.bf16.bf16.f32 " \
        "{%0,%1,%2,%3}, {%4,%5,%6,%7}, {%8,%9}, {%0,%1,%2,%3};" \
        : "+f"((c)[0]), "+f"((c)[1]), "+f"((c)[2]), "+f"((c)[3]) \
        : "r"((a)[0]), "r"((a)[1]), "r"((a)[2]), "r"((a)[3]), "r"(b0v), "r"(b1v))

#define CP_ASYNC16(dst_u32, src_ptr) \
    asm volatile("cp.async.cg.shared.global [%0], [%1], 16;" :: "r"(dst_u32), "l"(src_ptr) : "memory")
#define CP_COMMIT() asm volatile("cp.async.commit_group;" ::: "memory")
#define CP_WAIT(n)  asm volatile("cp.async.wait_group %0;" :: "n"(n) : "memory")

// ================= K0: dtype detect =================
__global__ void k_detect(const int* __restrict__ ei32) {
    if (threadIdx.x == 0 && blockIdx.x == 0) {
        int nz = 0;
        #pragma unroll 8
        for (int i = 0; i < 128; i++) nz |= ei32[2 * i + 1];
        g_is64 = (nz == 0) ? 1 : 0;
    }
}
__device__ __forceinline__ int load_idx(const void* ei, int is64, int pos) {
    if (is64) return (int)((const long long*)ei)[pos];
    return ((const int*)ei)[pos];
}

// ================= degree / CSR build =================
__global__ void k_zero_deg() {
    int i = blockIdx.x * blockDim.x + threadIdx.x;
    if (i < N_NODES) g_deg[i] = 0;
}
__global__ void k_hist(const void* __restrict__ ei) {
    int e = blockIdx.x * blockDim.x + threadIdx.x;
    if (e < N_EDGES) {
        int col = load_idx(ei, g_is64, N_EDGES + e);
        if ((unsigned)col < (unsigned)N_NODES) atomicAdd(&g_deg[col], 1);
    }
}
__global__ void k_scan1() {
    __shared__ int sh[256];
    int i = blockIdx.x * 256 + threadIdx.x;
    int v = (i < N_NODES) ? g_deg[i] : 0;
    sh[threadIdx.x] = v; __syncthreads();
    for (int off = 128; off > 0; off >>= 1) {
        if (threadIdx.x < off) sh[threadIdx.x] += sh[threadIdx.x + off];
        __syncthreads();
    }
    if (threadIdx.x == 0) g_bsum[blockIdx.x] = sh[0];
}
__global__ void k_scan2(int nblk) {
    __shared__ int sh[256];
    int t = threadIdx.x;
    int v = (t < nblk) ? g_bsum[t] : 0;
    sh[t] = v; __syncthreads();
    for (int off = 1; off < 256; off <<= 1) {
        int u = (t >= off) ? sh[t - off] : 0;
        __syncthreads(); sh[t] += u; __syncthreads();
    }
    g_boff[t] = sh[t] - v;
    if (t == 255) g_rowptr[N_NODES] = sh[255];
}
__global__ void k_scan3() {
    __shared__ int sh[256];
    int t = threadIdx.x;
    int i = blockIdx.x * 256 + t;
    int v = (i < N_NODES) ? g_deg[i] : 0;
    sh[t] = v; __syncthreads();
    for (int off = 1; off < 256; off <<= 1) {
        int u = (t >= off) ? sh[t - off] : 0;
        __syncthreads(); sh[t] += u; __syncthreads();
    }
    if (i < N_NODES) {
        int excl = sh[t] - v + g_boff[blockIdx.x];
        g_rowptr[i] = excl;
        g_cursor[i] = excl;
    }
}
__global__ void k_fill(const void* __restrict__ ei) {
    int e = blockIdx.x * blockDim.x + threadIdx.x;
    if (e < N_EDGES) {
        int is64 = g_is64;
        int row = load_idx(ei, is64, e);
        int col = load_idx(ei, is64, N_EDGES + e);
        if ((unsigned)row < (unsigned)N_NODES && (unsigned)col < (unsigned)N_NODES) {
            int pos = atomicAdd(&g_cursor[col], 1);
            if ((unsigned)pos < (unsigned)N_EDGES) g_esrc[pos] = row;
        }
    }
}

// ================= K-prep: transpose + bf16-split + swizzle weights =================
__global__ void k_prep(const float* __restrict__ Wsrc,
                       const float* __restrict__ Wdst,
                       const float* __restrict__ Wself) {
    int idx = blockIdx.x * blockDim.x + threadIdx.x;
    if (idx >= 3 * D * D) return;
    int m = idx >> 16;
    int rem = idx & 65535;
    int k = rem >> 8;
    int n = rem & 255;
    const float* W = (m == 0) ? Wsrc : (m == 1) ? Wdst : Wself;
    float w = W[k * D + n];
    __nv_bfloat16 hi = __float2bfloat16(w);
    __nv_bfloat16 lo = __float2bfloat16(w - __bfloat162float(hi));
    int ntile = n >> 6, r = n & 63;
    int kc = k >> 6, kl = k & 63;
    uint32_t off = swz((uint32_t)(r * 128 + kl * 2));
    size_t blk_hi = (size_t)(((m * 2 + 0) * 4 + ntile) * 4 + kc) * 8192;
    size_t blk_lo = (size_t)(((m * 2 + 1) * 4 + ntile) * 4 + kc) * 8192;
    *(__nv_bfloat16*)(g_wt + blk_hi + off) = hi;
    *(__nv_bfloat16*)(g_wt + blk_lo + off) = lo;
}

// ================= K-asplit: pre-split x into swizzled bf16 hi/lo tiles =================
// unit = 8 consecutive k-elements (16B dst). Total units = MTILES*128*32.
__global__ void k_asplit(const float* __restrict__ x) {
    int idx = blockIdx.x * blockDim.x + threadIdx.x;
    if (idx >= MTILES * 128 * 32) return;
    int row = idx >> 5;            // 0 .. MTILES*128-1 (padded)
    int j   = idx & 31;            // k-unit
    int mt = row >> 7, ri = row & 127;
    int kc = j >> 3;
    int klb = (j & 7) * 16;        // byte offset of k within 128B row
    union { __nv_bfloat16 h[8]; uint4 u4; } H, L;
    H.u4 = make_uint4(0, 0, 0, 0); L.u4 = make_uint4(0, 0, 0, 0);
    if (row < N_NODES) {
        const float4* p = (const float4*)(x + (size_t)row * D + j * 8);
        float4 a = p[0], b = p[1];
        float f[8] = {a.x, a.y, a.z, a.w, b.x, b.y, b.z, b.w};
        #pragma unroll
        for (int q = 0; q < 8; q++) {
            __nv_bfloat16 h = __float2bfloat16(f[q]);
            H.h[q] = h;
            L.h[q] = __float2bfloat16(f[q] - __bfloat162float(h));
        }
    }
    size_t blk = (size_t)(mt * 4 + kc) * 16384;
    uint32_t sw = swz((uint32_t)(ri * 128 + klb));
    *(uint4*)(g_xhi + blk + sw) = H.u4;
    *(uint4*)(g_xlo + blk + sw) = L.u4;
}

// ================= split-bf16 mma.sync fused triple GEMM, cp.async double-buffered ====
// CTA: M=128, N=64, 3 matrices. 8 warps 4(m) x 2(n). K = 4 chunks of 64.
// stage = Ahi 16K | Alo 16K | B 48K  (80K); two stages.
#define STAGE 81920
#define SMEM_TOTAL_G (1024 + 2 * STAGE)

__global__ __launch_bounds__(256, 1)
void k_gemm_mma(const float* __restrict__ bsrc,
                const float* __restrict__ bdst,
                const float* __restrict__ bself,
                float* __restrict__ out) {
    extern __shared__ __align__(1024) char smem[];
    const uint32_t sbase = smem_u32(smem);
    const int tid = threadIdx.x;
    const int wid = tid >> 5;
    const int lid = tid & 31;
    const int m0 = blockIdx.y * 128;
    const int n0 = blockIdx.x * 64;
    const int wm = wid & 3;
    const int wn = wid >> 2;

    float* sb = (float*)(smem + 64);   // 192 bias floats
    if (tid < 64)       sb[tid] = bsrc[n0 + tid];
    else if (tid < 128) sb[tid] = bdst[n0 + tid - 64];
    else if (tid < 192) sb[tid] = bself[n0 + tid - 128];

    const int a_row = wm * 32 + (lid & 15);
    const int a_kh  = (lid >> 4) << 4;
    const int b_row = wn * 32 + (lid & 7) + ((lid >> 4) << 3);
    const int b_kh  = ((lid >> 3) & 1) << 4;

    float acc[3][2][4][4];
    #pragma unroll
    for (int m = 0; m < 3; m++)
        #pragma unroll
        for (int i = 0; i < 2; i++)
            #pragma unroll
            for (int j = 0; j < 4; j++)
                #pragma unroll
                for (int q = 0; q < 4; q++) acc[m][i][j][q] = 0.f;

    // ---- async stage loader: pure verbatim 16B copies ----
    auto load_stage = [&](int c, int s) {
        uint32_t dstA = sbase + 1024 + s * STAGE;
        const unsigned char* srcH = g_xhi + (size_t)(blockIdx.y * 4 + c) * 16384;
        const unsigned char* srcL = g_xlo + (size_t)(blockIdx.y * 4 + c) * 16384;
        #pragma unroll
        for (int it = 0; it < 4; it++) {
            int u = tid + it * 256;        // 0..1023
            CP_ASYNC16(dstA + u * 16, srcH + u * 16);
            CP_ASYNC16(dstA + 16384 + u * 16, srcL + u * 16);
        }
        uint32_t dstB = dstA + 32768;
        #pragma unroll
        for (int it = 0; it < 12; it++) {
            int t = tid + it * 256;        // 0..3071
            int op = t >> 9;
            int w  = t & 511;
            const unsigned char* srcB = g_wt + (size_t)((op * 4 + blockIdx.x) * 4 + c) * 8192 + w * 16;
            CP_ASYNC16(dstB + op * 8192 + w * 16, srcB);
        }
    };

    load_stage(0, 0);
    CP_COMMIT();

    for (int c = 0; c < 4; c++) {
        const int s = c & 1;
        if (c + 1 < 4) {
            load_stage(c + 1, s ^ 1);
            CP_COMMIT();
            CP_WAIT(1);
        } else {
            CP_WAIT(0);
        }
        __syncthreads();

        const uint32_t abase = sbase + 1024 + s * STAGE;
        const uint32_t bbase = abase + 32768;

        #pragma unroll
        for (int kk = 0; kk < 4; kk++) {
            const int kb = kk * 32;

            uint32_t af[2][2][4];
            #pragma unroll
            for (int mt = 0; mt < 2; mt++) {
                uint32_t off = swz((uint32_t)((a_row + mt * 16) * 128 + kb + a_kh));
                LDSM_X4(af[0][mt][0], af[0][mt][1], af[0][mt][2], af[0][mt][3], abase + off);
                LDSM_X4(af[1][mt][0], af[1][mt][1], af[1][mt][2], af[1][mt][3], abase + 16384 + off);
            }

            #pragma unroll
            for (int mat = 0; mat < 3; mat++) {
                uint32_t bf[2][4][2];
                #pragma unroll
                for (int sp = 0; sp < 2; sp++) {
                    uint32_t bb = bbase + (uint32_t)(mat * 2 + sp) * 8192;
                    #pragma unroll
                    for (int np = 0; np < 2; np++) {
                        uint32_t off = swz((uint32_t)((b_row + np * 16) * 128 + kb + b_kh));
                        LDSM_X4(bf[sp][np * 2][0], bf[sp][np * 2][1],
                                bf[sp][np * 2 + 1][0], bf[sp][np * 2 + 1][1],
                                bb + off);
                    }
                }
                #pragma unroll
                for (int mt = 0; mt < 2; mt++) {
                    #pragma unroll
                    for (int nt = 0; nt < 4; nt++) {
                        MMA_BF16(acc[mat][mt][nt], af[0][mt], bf[0][nt][0], bf[0][nt][1]); // hi*hi
                        MMA_BF16(acc[mat][mt][nt], af[0][mt], bf[1][nt][0], bf[1][nt][1]); // hi*lo
                        MMA_BF16(acc[mat][mt][nt], af[1][mt], bf[0][nt][0], bf[0][nt][1]); // lo*hi
                    }
                }
            }
        }
        __syncthreads();
    }

    // ---- epilogue ----
    const int qr = lid >> 2;
    const int qc = (lid & 3) * 2;
    #pragma unroll
    for (int mt = 0; mt < 2; mt++) {
        #pragma unroll
        for (int half = 0; half < 2; half++) {
            int row = m0 + wm * 32 + mt * 16 + qr + half * 8;
            if (row >= N_NODES) continue;
            float degf = (float)g_deg[row];
            #pragma unroll
            for (int nt = 0; nt < 4; nt++) {
                int cl = wn * 32 + nt * 8 + qc;
                float s0 = acc[0][mt][nt][half * 2 + 0] + sb[cl + 0];
                float s1 = acc[0][mt][nt][half * 2 + 1] + sb[cl + 1];
                float o0 = acc[2][mt][nt][half * 2 + 0] + sb[128 + cl + 0]
                         - degf * (acc[1][mt][nt][half * 2 + 0] + sb[64 + cl + 0]);
                float o1 = acc[2][mt][nt][half * 2 + 1] + sb[128 + cl + 1]
                         - degf * (acc[1][mt][nt][half * 2 + 1] + sb[64 + cl + 1]);
                *(float2*)&g_src[(size_t)row * D + n0 + cl] = make_float2(s0, s1);
                *(float2*)&out[(size_t)row * D + n0 + cl]   = make_float2(o0, o1);
            }
        }
    }
}

// ================= K6: gather reduce: out[v] += sum_{nbr} SRC[nbr] =================
__global__ __launch_bounds__(256)
void k_reduce(float* __restrict__ out) {
    const int v = blockIdx.x;
    const int dim = threadIdx.x;
    const int s = g_rowptr[v];
    const int e = g_rowptr[v + 1];

    __shared__ int nbr[512];

    float acc = 0.f;
    for (int base = s; base < e; base += 512) {
        int cnt = min(512, e - base);
        for (int i = threadIdx.x; i < cnt; i += 256) nbr[i] = g_esrc[base + i];
        __syncthreads();
        int i = 0;
        for (; i + 4 <= cnt; i += 4) {
            float x0 = g_src[(size_t)nbr[i + 0] * D + dim];
            float x1 = g_src[(size_t)nbr[i + 1] * D + dim];
            float x2 = g_src[(size_t)nbr[i + 2] * D + dim];
            float x3 = g_src[(size_t)nbr[i + 3] * D + dim];
            acc += (x0 + x1) + (x2 + x3);
        }
        for (; i < cnt; i++) acc += g_src[(size_t)nbr[i] * D + dim];
        __syncthreads();
    }
    if (e > s) out[(size_t)v * D + dim] += acc;
}

// ================= launch =================
extern "C" void kernel_launch(void* const* d_in, const int* in_sizes, int n_in,
                              void* d_out, int out_size) {
    const float* x     = (const float*)d_in[0];
    const void*  ei    = d_in[1];
    const float* Wsrc  = (const float*)d_in[2];
    const float* bsrc  = (const float*)d_in[3];
    const float* Wdst  = (const float*)d_in[4];
    const float* bdst  = (const float*)d_in[5];
    const float* Wself = (const float*)d_in[6];
    const float* bself = (const float*)d_in[7];
    float* out = (float*)d_out;

    const int NB = (N_NODES + 255) / 256;      // 196

    k_detect<<<1, 32>>>((const int*)ei);
    k_zero_deg<<<NB, 256>>>();
    k_hist<<<(N_EDGES + 255) / 256, 256>>>(ei);
    k_scan1<<<NB, 256>>>();
    k_scan2<<<1, 256>>>(NB);
    k_scan3<<<NB, 256>>>();
    k_fill<<<(N_EDGES + 255) / 256, 256>>>(ei);
    k_prep<<<(3 * D * D + 255) / 256, 256>>>(Wsrc, Wdst, Wself);
    k_asplit<<<(MTILES * 128 * 32 + 255) / 256, 256>>>(x);

    cudaFuncSetAttribute(k_gemm_mma, cudaFuncAttributeMaxDynamicSharedMemorySize, SMEM_TOTAL_G);
    dim3 ggrid(4, MTILES);                     // (4, 391)
    k_gemm_mma<<<ggrid, 256, SMEM_TOTAL_G>>>(bsrc, bdst, bself, out);

    k_reduce<<<N_NODES, 256>>>(out);
}

// round 8
// speedup vs baseline: 2.6108x; 1.2983x over previous
#include <cuda_runtime.h>
#include <cuda_fp16.h>
#include <stdint.h>

#define N_NODES 50000
#define N_EDGES 800000
#define D 256
#define MTILES 391           // ceil(50000/128)

// ================= device scratch (no dynamic allocation allowed) =================
__device__ float g_src[(size_t)N_NODES * D];   // SRC = x@W_src + b_src (51.2 MB)
__device__ int   g_deg[N_NODES];
__device__ int   g_rowptr[N_NODES + 1];
__device__ int   g_cursor[N_NODES];
__device__ int   g_esrc[N_EDGES];
__device__ int   g_is64;
__device__ int   g_bsum[256];
__device__ int   g_boff[256];
// pre-transposed, pre-swizzled fp16 weights:
// block id = (mat*4 + ntile)*4 + kchunk, each 8192 B (64n x 64k fp16, SW128)
__device__ __align__(256) unsigned char g_wt[3 * 4 * 4 * 8192];
// pre-converted, pre-swizzled fp16 activations: block id = mtile*4 + kchunk, each 16384 B
__device__ __align__(256) unsigned char g_xh[(size_t)MTILES * 4 * 16384];

__device__ __forceinline__ uint32_t smem_u32(const void* p) {
    uint32_t a;
    asm("{ .reg .u64 t; cvta.to.shared.u64 t, %1; cvt.u32.u64 %0, t; }" : "=r"(a) : "l"(p));
    return a;
}
__device__ __forceinline__ uint32_t swz(uint32_t off) { return off ^ ((off >> 3) & 0x70); }

#define LDSM_X4(r0, r1, r2, r3, addr) \
    asm volatile("ldmatrix.sync.aligned.m8n8.x4.shared.b16 {%0,%1,%2,%3}, [%4];" \
        : "=r"(r0), "=r"(r1), "=r"(r2), "=r"(r3) : "r"(addr))

#define MMA_FP16(c, a, b0v, b1v) \
    asm volatile("mma.sync.aligned.m16n8k16.row.col.f32.f16.f16.f32 " \
        "{%0,%1,%2,%3}, {%4,%5,%6,%7}, {%8,%9}, {%0,%1,%2,%3};" \
        : "+f"((c)[0]), "+f"((c)[1]), "+f"((c)[2]), "+f"((c)[3]) \
        : "r"((a)[0]), "r"((a)[1]), "r"((a)[2]), "r"((a)[3]), "r"(b0v), "r"(b1v))

#define CP_ASYNC16(dst_u32, src_ptr) \
    asm volatile("cp.async.cg.shared.global [%0], [%1], 16;" :: "r"(dst_u32), "l"(src_ptr) : "memory")
#define CP_COMMIT() asm volatile("cp.async.commit_group;" ::: "memory")
#define CP_WAIT(n)  asm volatile("cp.async.wait_group %0;" :: "n"(n) : "memory")

// ================= K0: dtype detect =================
__global__ void k_detect(const int* __restrict__ ei32) {
    if (threadIdx.x == 0 && blockIdx.x == 0) {
        int nz = 0;
        #pragma unroll 8
        for (int i = 0; i < 128; i++) nz |= ei32[2 * i + 1];
        g_is64 = (nz == 0) ? 1 : 0;
    }
}
__device__ __forceinline__ int load_idx(const void* ei, int is64, int pos) {
    if (is64) return (int)((const long long*)ei)[pos];
    return ((const int*)ei)[pos];
}

// ================= degree / CSR build =================
__global__ void k_zero_deg() {
    int i = blockIdx.x * blockDim.x + threadIdx.x;
    if (i < N_NODES) g_deg[i] = 0;
}
__global__ void k_hist(const void* __restrict__ ei) {
    int e = blockIdx.x * blockDim.x + threadIdx.x;
    if (e < N_EDGES) {
        int col = load_idx(ei, g_is64, N_EDGES + e);
        if ((unsigned)col < (unsigned)N_NODES) atomicAdd(&g_deg[col], 1);
    }
}
__global__ void k_scan1() {
    __shared__ int sh[256];
    int i = blockIdx.x * 256 + threadIdx.x;
    int v = (i < N_NODES) ? g_deg[i] : 0;
    sh[threadIdx.x] = v; __syncthreads();
    for (int off = 128; off > 0; off >>= 1) {
        if (threadIdx.x < off) sh[threadIdx.x] += sh[threadIdx.x + off];
        __syncthreads();
    }
    if (threadIdx.x == 0) g_bsum[blockIdx.x] = sh[0];
}
__global__ void k_scan2(int nblk) {
    __shared__ int sh[256];
    int t = threadIdx.x;
    int v = (t < nblk) ? g_bsum[t] : 0;
    sh[t] = v; __syncthreads();
    for (int off = 1; off < 256; off <<= 1) {
        int u = (t >= off) ? sh[t - off] : 0;
        __syncthreads(); sh[t] += u; __syncthreads();
    }
    g_boff[t] = sh[t] - v;
    if (t == 255) g_rowptr[N_NODES] = sh[255];
}
__global__ void k_scan3() {
    __shared__ int sh[256];
    int t = threadIdx.x;
    int i = blockIdx.x * 256 + t;
    int v = (i < N_NODES) ? g_deg[i] : 0;
    sh[t] = v; __syncthreads();
    for (int off = 1; off < 256; off <<= 1) {
        int u = (t >= off) ? sh[t - off] : 0;
        __syncthreads(); sh[t] += u; __syncthreads();
    }
    if (i < N_NODES) {
        int excl = sh[t] - v + g_boff[blockIdx.x];
        g_rowptr[i] = excl;
        g_cursor[i] = excl;
    }
}
__global__ void k_fill(const void* __restrict__ ei) {
    int e = blockIdx.x * blockDim.x + threadIdx.x;
    if (e < N_EDGES) {
        int is64 = g_is64;
        int row = load_idx(ei, is64, e);
        int col = load_idx(ei, is64, N_EDGES + e);
        if ((unsigned)row < (unsigned)N_NODES && (unsigned)col < (unsigned)N_NODES) {
            int pos = atomicAdd(&g_cursor[col], 1);
            if ((unsigned)pos < (unsigned)N_EDGES) g_esrc[pos] = row;
        }
    }
}

// ================= K-prep: transpose + fp16 + swizzle weights =================
__global__ void k_prep(const float* __restrict__ Wsrc,
                       const float* __restrict__ Wdst,
                       const float* __restrict__ Wself) {
    int idx = blockIdx.x * blockDim.x + threadIdx.x;
    if (idx >= 3 * D * D) return;
    int m = idx >> 16;
    int rem = idx & 65535;
    int k = rem >> 8;
    int n = rem & 255;
    const float* W = (m == 0) ? Wsrc : (m == 1) ? Wdst : Wself;
    __half h = __float2half(W[k * D + n]);
    int ntile = n >> 6, r = n & 63;
    int kc = k >> 6, kl = k & 63;
    uint32_t off = swz((uint32_t)(r * 128 + kl * 2));
    size_t blk = (size_t)((m * 4 + ntile) * 4 + kc) * 8192;
    *(__half*)(g_wt + blk + off) = h;
}

// ================= K-aconv: x -> fp16, swizzled tiles =================
// unit = 8 consecutive k-elements (16B dst). Total units = MTILES*128*32.
__global__ void k_aconv(const float* __restrict__ x) {
    int idx = blockIdx.x * blockDim.x + threadIdx.x;
    if (idx >= MTILES * 128 * 32) return;
    int row = idx >> 5;
    int j   = idx & 31;
    int mt = row >> 7, ri = row & 127;
    int kc = j >> 3;
    int klb = (j & 7) * 16;
    union { __half h[8]; uint4 u4; } H;
    H.u4 = make_uint4(0, 0, 0, 0);
    if (row < N_NODES) {
        const float4* p = (const float4*)(x + (size_t)row * D + j * 8);
        float4 a = p[0], b = p[1];
        float f[8] = {a.x, a.y, a.z, a.w, b.x, b.y, b.z, b.w};
        #pragma unroll
        for (int q = 0; q < 8; q++) H.h[q] = __float2half(f[q]);
    }
    size_t blk = (size_t)(mt * 4 + kc) * 16384;
    uint32_t sw = swz((uint32_t)(ri * 128 + klb));
    *(uint4*)(g_xh + blk + sw) = H.u4;
}

// ================= single-pass fp16 mma.sync fused triple GEMM ====
// CTA: M=128, N=64, 3 matrices. 8 warps 4(m) x 2(n). K = 4 chunks of 64.
// stage = A 16K | B 24K (40K); two stages (83K total SMEM).
#define STAGE 40960
#define SMEM_TOTAL_G (1024 + 2 * STAGE)

__global__ __launch_bounds__(256, 1)
void k_gemm_mma(const float* __restrict__ bsrc,
                const float* __restrict__ bdst,
                const float* __restrict__ bself,
                float* __restrict__ out) {
    extern __shared__ __align__(1024) char smem[];
    const uint32_t sbase = smem_u32(smem);
    const int tid = threadIdx.x;
    const int wid = tid >> 5;
    const int lid = tid & 31;
    const int m0 = blockIdx.y * 128;
    const int n0 = blockIdx.x * 64;
    const int wm = wid & 3;
    const int wn = wid >> 2;

    float* sb = (float*)(smem + 64);   // 192 bias floats
    if (tid < 64)       sb[tid] = bsrc[n0 + tid];
    else if (tid < 128) sb[tid] = bdst[n0 + tid - 64];
    else if (tid < 192) sb[tid] = bself[n0 + tid - 128];

    const int a_row = wm * 32 + (lid & 15);
    const int a_kh  = (lid >> 4) << 4;
    const int b_row = wn * 32 + (lid & 7) + ((lid >> 4) << 3);
    const int b_kh  = ((lid >> 3) & 1) << 4;

    float acc[3][2][4][4];
    #pragma unroll
    for (int m = 0; m < 3; m++)
        #pragma unroll
        for (int i = 0; i < 2; i++)
            #pragma unroll
            for (int j = 0; j < 4; j++)
                #pragma unroll
                for (int q = 0; q < 4; q++) acc[m][i][j][q] = 0.f;

    // ---- async stage loader: pure verbatim 16B copies ----
    auto load_stage = [&](int c, int s) {
        uint32_t dstA = sbase + 1024 + s * STAGE;
        const unsigned char* srcA = g_xh + (size_t)(blockIdx.y * 4 + c) * 16384;
        #pragma unroll
        for (int it = 0; it < 4; it++) {
            int u = tid + it * 256;        // 0..1023
            CP_ASYNC16(dstA + u * 16, srcA + u * 16);
        }
        uint32_t dstB = dstA + 16384;
        #pragma unroll
        for (int it = 0; it < 6; it++) {
            int t = tid + it * 256;        // 0..1535
            int op = t >> 9;               // mat
            int w  = t & 511;
            const unsigned char* srcB = g_wt + (size_t)((op * 4 + blockIdx.x) * 4 + c) * 8192 + w * 16;
            CP_ASYNC16(dstB + op * 8192 + w * 16, srcB);
        }
    };

    load_stage(0, 0);
    CP_COMMIT();

    for (int c = 0; c < 4; c++) {
        const int s = c & 1;
        if (c + 1 < 4) {
            load_stage(c + 1, s ^ 1);
            CP_COMMIT();
            CP_WAIT(1);
        } else {
            CP_WAIT(0);
        }
        __syncthreads();

        const uint32_t abase = sbase + 1024 + s * STAGE;
        const uint32_t bbase = abase + 16384;

        #pragma unroll
        for (int kk = 0; kk < 4; kk++) {
            const int kb = kk * 32;

            uint32_t af[2][4];
            #pragma unroll
            for (int mt = 0; mt < 2; mt++) {
                uint32_t off = swz((uint32_t)((a_row + mt * 16) * 128 + kb + a_kh));
                LDSM_X4(af[mt][0], af[mt][1], af[mt][2], af[mt][3], abase + off);
            }

            #pragma unroll
            for (int mat = 0; mat < 3; mat++) {
                uint32_t bf[4][2];
                uint32_t bb = bbase + (uint32_t)mat * 8192;
                #pragma unroll
                for (int np = 0; np < 2; np++) {
                    uint32_t off = swz((uint32_t)((b_row + np * 16) * 128 + kb + b_kh));
                    LDSM_X4(bf[np * 2][0], bf[np * 2][1],
                            bf[np * 2 + 1][0], bf[np * 2 + 1][1],
                            bb + off);
                }
                #pragma unroll
                for (int mt = 0; mt < 2; mt++) {
                    #pragma unroll
                    for (int nt = 0; nt < 4; nt++) {
                        MMA_FP16(acc[mat][mt][nt], af[mt], bf[nt][0], bf[nt][1]);
                    }
                }
            }
        }
        __syncthreads();
    }

    // ---- epilogue ----
    const int qr = lid >> 2;
    const int qc = (lid & 3) * 2;
    #pragma unroll
    for (int mt = 0; mt < 2; mt++) {
        #pragma unroll
        for (int half = 0; half < 2; half++) {
            int row = m0 + wm * 32 + mt * 16 + qr + half * 8;
            if (row >= N_NODES) continue;
            float degf = (float)g_deg[row];
            #pragma unroll
            for (int nt = 0; nt < 4; nt++) {
                int cl = wn * 32 + nt * 8 + qc;
                float s0 = acc[0][mt][nt][half * 2 + 0] + sb[cl + 0];
                float s1 = acc[0][mt][nt][half * 2 + 1] + sb[cl + 1];
                float o0 = acc[2][mt][nt][half * 2 + 0] + sb[128 + cl + 0]
                         - degf * (acc[1][mt][nt][half * 2 + 0] + sb[64 + cl + 0]);
                float o1 = acc[2][mt][nt][half * 2 + 1] + sb[128 + cl + 1]
                         - degf * (acc[1][mt][nt][half * 2 + 1] + sb[64 + cl + 1]);
                *(float2*)&g_src[(size_t)row * D + n0 + cl] = make_float2(s0, s1);
                *(float2*)&out[(size_t)row * D + n0 + cl]   = make_float2(o0, o1);
            }
        }
    }
}

// ================= K6: gather reduce: out[v] += sum_{nbr} SRC[nbr] =================
__global__ __launch_bounds__(256)
void k_reduce(float* __restrict__ out) {
    const int v = blockIdx.x;
    const int dim = threadIdx.x;
    const int s = g_rowptr[v];
    const int e = g_rowptr[v + 1];

    __shared__ int nbr[512];

    float acc = 0.f;
    for (int base = s; base < e; base += 512) {
        int cnt = min(512, e - base);
        for (int i = threadIdx.x; i < cnt; i += 256) nbr[i] = g_esrc[base + i];
        __syncthreads();
        int i = 0;
        for (; i + 4 <= cnt; i += 4) {
            float x0 = g_src[(size_t)nbr[i + 0] * D + dim];
            float x1 = g_src[(size_t)nbr[i + 1] * D + dim];
            float x2 = g_src[(size_t)nbr[i + 2] * D + dim];
            float x3 = g_src[(size_t)nbr[i + 3] * D + dim];
            acc += (x0 + x1) + (x2 + x3);
        }
        for (; i < cnt; i++) acc += g_src[(size_t)nbr[i] * D + dim];
        __syncthreads();
    }
    if (e > s) out[(size_t)v * D + dim] += acc;
}

// ================= launch =================
extern "C" void kernel_launch(void* const* d_in, const int* in_sizes, int n_in,
                              void* d_out, int out_size) {
    const float* x     = (const float*)d_in[0];
    const void*  ei    = d_in[1];
    const float* Wsrc  = (const float*)d_in[2];
    const float* bsrc  = (const float*)d_in[3];
    const float* Wdst  = (const float*)d_in[4];
    const float* bdst  = (const float*)d_in[5];
    const float* Wself = (const float*)d_in[6];
    const float* bself = (const float*)d_in[7];
    float* out = (float*)d_out;

    const int NB = (N_NODES + 255) / 256;      // 196

    k_detect<<<1, 32>>>((const int*)ei);
    k_zero_deg<<<NB, 256>>>();
    k_hist<<<(N_EDGES + 255) / 256, 256>>>(ei);
    k_scan1<<<NB, 256>>>();
    k_scan2<<<1, 256>>>(NB);
    k_scan3<<<NB, 256>>>();
    k_fill<<<(N_EDGES + 255) / 256, 256>>>(ei);
    k_prep<<<(3 * D * D + 255) / 256, 256>>>(Wsrc, Wdst, Wself);
    k_aconv<<<(MTILES * 128 * 32 + 255) / 256, 256>>>(x);

    cudaFuncSetAttribute(k_gemm_mma, cudaFuncAttributeMaxDynamicSharedMemorySize, SMEM_TOTAL_G);
    dim3 ggrid(4, MTILES);                     // (4, 391)
    k_gemm_mma<<<ggrid, 256, SMEM_TOTAL_G>>>(bsrc, bdst, bself, out);

    k_reduce<<<N_NODES, 256>>>(out);
}

// round 9
// speedup vs baseline: 3.4880x; 1.3360x over previous
#include <cuda_runtime.h>
#include <cuda_fp16.h>
#include <stdint.h>

#define N_NODES 50000
#define N_EDGES 800000
#define D 256
#define MTILES 391           // ceil(50000/128)

// ================= device scratch (no dynamic allocation allowed) =================
__device__ __half g_srch[(size_t)N_NODES * D]; // SRC = x@W_src + b_src (fp16, 25.6 MB)
__device__ int   g_deg[N_NODES];
__device__ int   g_rowptr[N_NODES + 1];
__device__ int   g_cursor[N_NODES];
__device__ int   g_esrc[N_EDGES];
__device__ int   g_is64;
__device__ int   g_bsum[256];
__device__ int   g_boff[256];
// pre-transposed, pre-swizzled fp16 weights:
// block id = (mat*4 + ntile)*4 + kchunk, each 8192 B (64n x 64k fp16, SW128)
__device__ __align__(256) unsigned char g_wt[3 * 4 * 4 * 8192];
// pre-converted, pre-swizzled fp16 activations: block id = mtile*4 + kchunk, each 16384 B
__device__ __align__(256) unsigned char g_xh[(size_t)MTILES * 4 * 16384];

__device__ __forceinline__ uint32_t smem_u32(const void* p) {
    uint32_t a;
    asm("{ .reg .u64 t; cvta.to.shared.u64 t, %1; cvt.u32.u64 %0, t; }" : "=r"(a) : "l"(p));
    return a;
}
__device__ __forceinline__ uint32_t swz(uint32_t off) { return off ^ ((off >> 3) & 0x70); }

#define LDSM_X4(r0, r1, r2, r3, addr) \
    asm volatile("ldmatrix.sync.aligned.m8n8.x4.shared.b16 {%0,%1,%2,%3}, [%4];" \
        : "=r"(r0), "=r"(r1), "=r"(r2), "=r"(r3) : "r"(addr))

#define MMA_FP16(c, a, b0v, b1v) \
    asm volatile("mma.sync.aligned.m16n8k16.row.col.f32.f16.f16.f32 " \
        "{%0,%1,%2,%3}, {%4,%5,%6,%7}, {%8,%9}, {%0,%1,%2,%3};" \
        : "+f"((c)[0]), "+f"((c)[1]), "+f"((c)[2]), "+f"((c)[3]) \
        : "r"((a)[0]), "r"((a)[1]), "r"((a)[2]), "r"((a)[3]), "r"(b0v), "r"(b1v))

#define CP_ASYNC16(dst_u32, src_ptr) \
    asm volatile("cp.async.cg.shared.global [%0], [%1], 16;" :: "r"(dst_u32), "l"(src_ptr) : "memory")
#define CP_COMMIT() asm volatile("cp.async.commit_group;" ::: "memory")
#define CP_WAIT(n)  asm volatile("cp.async.wait_group %0;" :: "n"(n) : "memory")

__device__ __forceinline__ int load_idx(const void* ei, int is64, int pos) {
    if (is64) return (int)((const long long*)ei)[pos];
    return ((const int*)ei)[pos];
}

// ================= K1: zero degree histogram + dtype detect (fused) =================
__global__ void k_zero_deg(const int* __restrict__ ei32) {
    int i = blockIdx.x * blockDim.x + threadIdx.x;
    if (i < N_NODES) g_deg[i] = 0;
    if (blockIdx.x == 0 && threadIdx.x == 0) {
        int nz = 0;
        #pragma unroll 8
        for (int q = 0; q < 128; q++) nz |= ei32[2 * q + 1];
        g_is64 = (nz == 0) ? 1 : 0;
    }
}
__global__ void k_hist(const void* __restrict__ ei) {
    int e = blockIdx.x * blockDim.x + threadIdx.x;
    if (e < N_EDGES) {
        int col = load_idx(ei, g_is64, N_EDGES + e);
        if ((unsigned)col < (unsigned)N_NODES) atomicAdd(&g_deg[col], 1);
    }
}
__global__ void k_scan1() {
    __shared__ int sh[256];
    int i = blockIdx.x * 256 + threadIdx.x;
    int v = (i < N_NODES) ? g_deg[i] : 0;
    sh[threadIdx.x] = v; __syncthreads();
    for (int off = 128; off > 0; off >>= 1) {
        if (threadIdx.x < off) sh[threadIdx.x] += sh[threadIdx.x + off];
        __syncthreads();
    }
    if (threadIdx.x == 0) g_bsum[blockIdx.x] = sh[0];
}
__global__ void k_scan2(int nblk) {
    __shared__ int sh[256];
    int t = threadIdx.x;
    int v = (t < nblk) ? g_bsum[t] : 0;
    sh[t] = v; __syncthreads();
    for (int off = 1; off < 256; off <<= 1) {
        int u = (t >= off) ? sh[t - off] : 0;
        __syncthreads(); sh[t] += u; __syncthreads();
    }
    g_boff[t] = sh[t] - v;
    if (t == 255) g_rowptr[N_NODES] = sh[255];
}
__global__ void k_scan3() {
    __shared__ int sh[256];
    int t = threadIdx.x;
    int i = blockIdx.x * 256 + t;
    int v = (i < N_NODES) ? g_deg[i] : 0;
    sh[t] = v; __syncthreads();
    for (int off = 1; off < 256; off <<= 1) {
        int u = (t >= off) ? sh[t - off] : 0;
        __syncthreads(); sh[t] += u; __syncthreads();
    }
    if (i < N_NODES) {
        int excl = sh[t] - v + g_boff[blockIdx.x];
        g_rowptr[i] = excl;
        g_cursor[i] = excl;
    }
}
__global__ void k_fill(const void* __restrict__ ei) {
    int e = blockIdx.x * blockDim.x + threadIdx.x;
    if (e < N_EDGES) {
        int is64 = g_is64;
        int row = load_idx(ei, is64, e);
        int col = load_idx(ei, is64, N_EDGES + e);
        if ((unsigned)row < (unsigned)N_NODES && (unsigned)col < (unsigned)N_NODES) {
            int pos = atomicAdd(&g_cursor[col], 1);
            if ((unsigned)pos < (unsigned)N_EDGES) g_esrc[pos] = row;
        }
    }
}

// ================= K-prep: transpose + fp16 + swizzle weights =================
__global__ void k_prep(const float* __restrict__ Wsrc,
                       const float* __restrict__ Wdst,
                       const float* __restrict__ Wself) {
    int idx = blockIdx.x * blockDim.x + threadIdx.x;
    if (idx >= 3 * D * D) return;
    int m = idx >> 16;
    int rem = idx & 65535;
    int k = rem >> 8;
    int n = rem & 255;
    const float* W = (m == 0) ? Wsrc : (m == 1) ? Wdst : Wself;
    __half h = __float2half(W[k * D + n]);
    int ntile = n >> 6, r = n & 63;
    int kc = k >> 6, kl = k & 63;
    uint32_t off = swz((uint32_t)(r * 128 + kl * 2));
    size_t blk = (size_t)((m * 4 + ntile) * 4 + kc) * 8192;
    *(__half*)(g_wt + blk + off) = h;
}

// ================= K-aconv: x -> fp16, swizzled tiles =================
__global__ void k_aconv(const float* __restrict__ x) {
    int idx = blockIdx.x * blockDim.x + threadIdx.x;
    if (idx >= MTILES * 128 * 32) return;
    int row = idx >> 5;
    int j   = idx & 31;
    int mt = row >> 7, ri = row & 127;
    int kc = j >> 3;
    int klb = (j & 7) * 16;
    union { __half h[8]; uint4 u4; } H;
    H.u4 = make_uint4(0, 0, 0, 0);
    if (row < N_NODES) {
        const float4* p = (const float4*)(x + (size_t)row * D + j * 8);
        float4 a = p[0], b = p[1];
        float f[8] = {a.x, a.y, a.z, a.w, b.x, b.y, b.z, b.w};
        #pragma unroll
        for (int q = 0; q < 8; q++) H.h[q] = __float2half(f[q]);
    }
    size_t blk = (size_t)(mt * 4 + kc) * 16384;
    uint32_t sw = swz((uint32_t)(ri * 128 + klb));
    *(uint4*)(g_xh + blk + sw) = H.u4;
}

// ================= single-pass fp16 mma.sync fused triple GEMM ====
// CTA: M=128, N=64, 3 matrices. 8 warps 4(m) x 2(n). K = 4 chunks of 64.
// stage = A 16K | B 24K (40K); two stages (83K total SMEM).
#define STAGE 40960
#define SMEM_TOTAL_G (1024 + 2 * STAGE)

__global__ __launch_bounds__(256, 1)
void k_gemm_mma(const float* __restrict__ bsrc,
                const float* __restrict__ bdst,
                const float* __restrict__ bself,
                float* __restrict__ out) {
    extern __shared__ __align__(1024) char smem[];
    const uint32_t sbase = smem_u32(smem);
    const int tid = threadIdx.x;
    const int wid = tid >> 5;
    const int lid = tid & 31;
    const int m0 = blockIdx.y * 128;
    const int n0 = blockIdx.x * 64;
    const int wm = wid & 3;
    const int wn = wid >> 2;

    float* sb = (float*)(smem + 64);   // 192 bias floats
    if (tid < 64)       sb[tid] = bsrc[n0 + tid];
    else if (tid < 128) sb[tid] = bdst[n0 + tid - 64];
    else if (tid < 192) sb[tid] = bself[n0 + tid - 128];

    const int a_row = wm * 32 + (lid & 15);
    const int a_kh  = (lid >> 4) << 4;
    const int b_row = wn * 32 + (lid & 7) + ((lid >> 4) << 3);
    const int b_kh  = ((lid >> 3) & 1) << 4;

    float acc[3][2][4][4];
    #pragma unroll
    for (int m = 0; m < 3; m++)
        #pragma unroll
        for (int i = 0; i < 2; i++)
            #pragma unroll
            for (int j = 0; j < 4; j++)
                #pragma unroll
                for (int q = 0; q < 4; q++) acc[m][i][j][q] = 0.f;

    auto load_stage = [&](int c, int s) {
        uint32_t dstA = sbase + 1024 + s * STAGE;
        const unsigned char* srcA = g_xh + (size_t)(blockIdx.y * 4 + c) * 16384;
        #pragma unroll
        for (int it = 0; it < 4; it++) {
            int u = tid + it * 256;
            CP_ASYNC16(dstA + u * 16, srcA + u * 16);
        }
        uint32_t dstB = dstA + 16384;
        #pragma unroll
        for (int it = 0; it < 6; it++) {
            int t = tid + it * 256;
            int op = t >> 9;
            int w  = t & 511;
            const unsigned char* srcB = g_wt + (size_t)((op * 4 + blockIdx.x) * 4 + c) * 8192 + w * 16;
            CP_ASYNC16(dstB + op * 8192 + w * 16, srcB);
        }
    };

    load_stage(0, 0);
    CP_COMMIT();

    for (int c = 0; c < 4; c++) {
        const int s = c & 1;
        if (c + 1 < 4) {
            load_stage(c + 1, s ^ 1);
            CP_COMMIT();
            CP_WAIT(1);
        } else {
            CP_WAIT(0);
        }
        __syncthreads();

        const uint32_t abase = sbase + 1024 + s * STAGE;
        const uint32_t bbase = abase + 16384;

        #pragma unroll
        for (int kk = 0; kk < 4; kk++) {
            const int kb = kk * 32;

            uint32_t af[2][4];
            #pragma unroll
            for (int mt = 0; mt < 2; mt++) {
                uint32_t off = swz((uint32_t)((a_row + mt * 16) * 128 + kb + a_kh));
                LDSM_X4(af[mt][0], af[mt][1], af[mt][2], af[mt][3], abase + off);
            }

            #pragma unroll
            for (int mat = 0; mat < 3; mat++) {
                uint32_t bf[4][2];
                uint32_t bb = bbase + (uint32_t)mat * 8192;
                #pragma unroll
                for (int np = 0; np < 2; np++) {
                    uint32_t off = swz((uint32_t)((b_row + np * 16) * 128 + kb + b_kh));
                    LDSM_X4(bf[np * 2][0], bf[np * 2][1],
                            bf[np * 2 + 1][0], bf[np * 2 + 1][1],
                            bb + off);
                }
                #pragma unroll
                for (int mt = 0; mt < 2; mt++) {
                    #pragma unroll
                    for (int nt = 0; nt < 4; nt++) {
                        MMA_FP16(acc[mat][mt][nt], af[mt], bf[nt][0], bf[nt][1]);
                    }
                }
            }
        }
        __syncthreads();
    }

    // ---- epilogue: SRC as fp16, OUT0 as f32 ----
    const int qr = lid >> 2;
    const int qc = (lid & 3) * 2;
    #pragma unroll
    for (int mt = 0; mt < 2; mt++) {
        #pragma unroll
        for (int half = 0; half < 2; half++) {
            int row = m0 + wm * 32 + mt * 16 + qr + half * 8;
            if (row >= N_NODES) continue;
            float degf = (float)g_deg[row];
            #pragma unroll
            for (int nt = 0; nt < 4; nt++) {
                int cl = wn * 32 + nt * 8 + qc;
                float s0 = acc[0][mt][nt][half * 2 + 0] + sb[cl + 0];
                float s1 = acc[0][mt][nt][half * 2 + 1] + sb[cl + 1];
                float o0 = acc[2][mt][nt][half * 2 + 0] + sb[128 + cl + 0]
                         - degf * (acc[1][mt][nt][half * 2 + 0] + sb[64 + cl + 0]);
                float o1 = acc[2][mt][nt][half * 2 + 1] + sb[128 + cl + 1]
                         - degf * (acc[1][mt][nt][half * 2 + 1] + sb[64 + cl + 1]);
                *(__half2*)&g_srch[(size_t)row * D + n0 + cl] = __floats2half2_rn(s0, s1);
                *(float2*)&out[(size_t)row * D + n0 + cl]     = make_float2(o0, o1);
            }
        }
    }
}

// ================= K6: gather reduce (fp16 SRC): out[v] += sum_{nbr} SRC[nbr] =========
// 128 threads per node; thread t owns dims [2t, 2t+1] via half2 loads.
__global__ __launch_bounds__(128)
void k_reduce(float* __restrict__ out) {
    const int v = blockIdx.x;
    const int s = g_rowptr[v];
    const int e = g_rowptr[v + 1];
    if (e == s) return;

    __shared__ int nbr[512];
    const int t = threadIdx.x;
    float accx = 0.f, accy = 0.f;

    for (int base = s; base < e; base += 512) {
        int cnt = min(512, e - base);
        for (int i = t; i < cnt; i += 128) nbr[i] = g_esrc[base + i];
        __syncthreads();
        int i = 0;
        for (; i + 4 <= cnt; i += 4) {
            __half2 a0 = *(const __half2*)&g_srch[(size_t)nbr[i + 0] * D + 2 * t];
            __half2 a1 = *(const __half2*)&g_srch[(size_t)nbr[i + 1] * D + 2 * t];
            __half2 a2 = *(const __half2*)&g_srch[(size_t)nbr[i + 2] * D + 2 * t];
            __half2 a3 = *(const __half2*)&g_srch[(size_t)nbr[i + 3] * D + 2 * t];
            float2 f0 = __half22float2(a0);
            float2 f1 = __half22float2(a1);
            float2 f2 = __half22float2(a2);
            float2 f3 = __half22float2(a3);
            accx += (f0.x + f1.x) + (f2.x + f3.x);
            accy += (f0.y + f1.y) + (f2.y + f3.y);
        }
        for (; i < cnt; i++) {
            float2 f = __half22float2(*(const __half2*)&g_srch[(size_t)nbr[i] * D + 2 * t]);
            accx += f.x; accy += f.y;
        }
        __syncthreads();
    }
    float2* o = (float2*)&out[(size_t)v * D + 2 * t];
    float2 cur = *o;
    cur.x += accx; cur.y += accy;
    *o = cur;
}

// ================= launch =================
extern "C" void kernel_launch(void* const* d_in, const int* in_sizes, int n_in,
                              void* d_out, int out_size) {
    const float* x     = (const float*)d_in[0];
    const void*  ei    = d_in[1];
    const float* Wsrc  = (const float*)d_in[2];
    const float* bsrc  = (const float*)d_in[3];
    const float* Wdst  = (const float*)d_in[4];
    const float* bdst  = (const float*)d_in[5];
    const float* Wself = (const float*)d_in[6];
    const float* bself = (const float*)d_in[7];
    float* out = (float*)d_out;

    const int NB = (N_NODES + 255) / 256;      // 196

    k_zero_deg<<<NB, 256>>>((const int*)ei);
    k_hist<<<(N_EDGES + 255) / 256, 256>>>(ei);
    k_scan1<<<NB, 256>>>();
    k_scan2<<<1, 256>>>(NB);
    k_scan3<<<NB, 256>>>();
    k_fill<<<(N_EDGES + 255) / 256, 256>>>(ei);
    k_prep<<<(3 * D * D + 255) / 256, 256>>>(Wsrc, Wdst, Wself);
    k_aconv<<<(MTILES * 128 * 32 + 255) / 256, 256>>>(x);

    cudaFuncSetAttribute(k_gemm_mma, cudaFuncAttributeMaxDynamicSharedMemorySize, SMEM_TOTAL_G);
    dim3 ggrid(4, MTILES);                     // (4, 391)
    k_gemm_mma<<<ggrid, 256, SMEM_TOTAL_G>>>(bsrc, bdst, bself, out);

    k_reduce<<<N_NODES, 128>>>(out);
}

// round 10
// speedup vs baseline: 4.2439x; 1.2167x over previous
#include <cuda_runtime.h>
#include <cuda_fp16.h>
#include <stdint.h>

#define N_NODES 50000
#define N_EDGES 800000
#define D 256
#define MTILES 391           // ceil(50000/128)
#define SCAN_BLOCKS 196      // ceil(50000/256)

// ================= device scratch (no dynamic allocation allowed) =================
__device__ __half g_srch[(size_t)N_NODES * D]; // SRC = x@W_src + b_src (fp16, 25.6 MB)
__device__ int   g_deg[N_NODES];
__device__ int   g_rowptr[N_NODES + 1];
__device__ int   g_cursor[N_NODES];
__device__ int   g_esrc[N_EDGES];
__device__ int   g_is64;
// decoupled-lookback scan state
__device__ int   g_agg[SCAN_BLOCKS];
__device__ int   g_pre[SCAN_BLOCKS];
__device__ int   g_st[SCAN_BLOCKS];            // 0 none, 1 aggregate ready, 2 inclusive ready
// pre-transposed, pre-swizzled fp16 weights:
// block id = (mat*4 + ntile)*4 + kchunk, each 8192 B (64n x 64k fp16, SW128)
__device__ __align__(256) unsigned char g_wt[3 * 4 * 4 * 8192];
// pre-converted, pre-swizzled fp16 activations: block id = mtile*4 + kchunk, each 16384 B
__device__ __align__(256) unsigned char g_xh[(size_t)MTILES * 4 * 16384];

__device__ __forceinline__ uint32_t smem_u32(const void* p) {
    uint32_t a;
    asm("{ .reg .u64 t; cvta.to.shared.u64 t, %1; cvt.u32.u64 %0, t; }" : "=r"(a) : "l"(p));
    return a;
}
__device__ __forceinline__ uint32_t swz(uint32_t off) { return off ^ ((off >> 3) & 0x70); }

#define LDSM_X4(r0, r1, r2, r3, addr) \
    asm volatile("ldmatrix.sync.aligned.m8n8.x4.shared.b16 {%0,%1,%2,%3}, [%4];" \
        : "=r"(r0), "=r"(r1), "=r"(r2), "=r"(r3) : "r"(addr))

#define MMA_FP16(c, a, b0v, b1v) \
    asm volatile("mma.sync.aligned.m16n8k16.row.col.f32.f16.f16.f32 " \
        "{%0,%1,%2,%3}, {%4,%5,%6,%7}, {%8,%9}, {%0,%1,%2,%3};" \
        : "+f"((c)[0]), "+f"((c)[1]), "+f"((c)[2]), "+f"((c)[3]) \
        : "r"((a)[0]), "r"((a)[1]), "r"((a)[2]), "r"((a)[3]), "r"(b0v), "r"(b1v))

#define CP_ASYNC16(dst_u32, src_ptr) \
    asm volatile("cp.async.cg.shared.global [%0], [%1], 16;" :: "r"(dst_u32), "l"(src_ptr) : "memory")
#define CP_COMMIT() asm volatile("cp.async.commit_group;" ::: "memory")
#define CP_WAIT(n)  asm volatile("cp.async.wait_group %0;" :: "n"(n) : "memory")

__device__ __forceinline__ int load_idx(const void* ei, int is64, int pos) {
    if (is64) return (int)((const long long*)ei)[pos];
    return ((const int*)ei)[pos];
}

// ================= K1: zero degree + scan state + dtype detect (fused) =================
__global__ void k_zero_deg(const int* __restrict__ ei32) {
    int i = blockIdx.x * blockDim.x + threadIdx.x;
    if (i < N_NODES) g_deg[i] = 0;
    if (i < SCAN_BLOCKS) g_st[i] = 0;
    if (blockIdx.x == 0 && threadIdx.x == 0) {
        int nz = 0;
        #pragma unroll 8
        for (int q = 0; q < 128; q++) nz |= ei32[2 * q + 1];
        g_is64 = (nz == 0) ? 1 : 0;
    }
}
__global__ void k_hist(const void* __restrict__ ei) {
    int e = blockIdx.x * blockDim.x + threadIdx.x;
    if (e < N_EDGES) {
        int col = load_idx(ei, g_is64, N_EDGES + e);
        if ((unsigned)col < (unsigned)N_NODES) atomicAdd(&g_deg[col], 1);
    }
}

// ================= single-pass decoupled-lookback exclusive scan =================
__global__ __launch_bounds__(256)
void k_scan() {
    __shared__ int sh[256];
    __shared__ int s_prefix;
    const int b = blockIdx.x;
    const int t = threadIdx.x;
    const int i = b * 256 + t;
    const int v = (i < N_NODES) ? g_deg[i] : 0;

    // inclusive Hillis-Steele scan within block
    sh[t] = v; __syncthreads();
    #pragma unroll
    for (int off = 1; off < 256; off <<= 1) {
        int u = (t >= off) ? sh[t - off] : 0;
        __syncthreads(); sh[t] += u; __syncthreads();
    }
    const int incl = sh[t];
    const int total = sh[255];

    // publish aggregate
    if (t == 0) {
        g_agg[b] = total;
        __threadfence();
        *(volatile int*)&g_st[b] = 1;
    }

    // warp 0: decoupled lookback for exclusive prefix of this block
    if (t < 32) {
        int prefix = 0;
        if (b > 0) {
            int look = b - 1;
            while (true) {
                int idx = look - t;      // lane t inspects block idx
                int st = 2, val = 0;
                if (idx >= 0) {
                    st = *(volatile int*)&g_st[idx];
                    if (st == 2)      val = *(volatile int*)&g_pre[idx];
                    else if (st == 1) val = *(volatile int*)&g_agg[idx];
                }
                unsigned done  = __ballot_sync(0xffffffff, st == 2 && idx >= 0) | ((look - 31 < 0) ? (1u << (look + 1 >= 32 ? 31 : look + 1)) : 0);
                // simpler: treat idx<0 lanes as done with val=0
                done = __ballot_sync(0xffffffff, st == 2);
                unsigned ready = __ballot_sync(0xffffffff, st >= 1);
                if (done) {
                    int fd = __ffs(done) - 1;              // closest finished block
                    unsigned need = (fd > 0) ? ((1u << fd) - 1) : 0;
                    if ((ready & need) == need) {
                        int contrib = (t <= fd) ? val : 0;
                        #pragma unroll
                        for (int o = 16; o > 0; o >>= 1)
                            contrib += __shfl_down_sync(0xffffffff, contrib, o);
                        prefix += __shfl_sync(0xffffffff, contrib, 0);
                        break;
                    }
                } else if (ready == 0xffffffffu && look >= 31) {
                    int contrib = val;
                    #pragma unroll
                    for (int o = 16; o > 0; o >>= 1)
                        contrib += __shfl_down_sync(0xffffffff, contrib, o);
                    prefix += __shfl_sync(0xffffffff, contrib, 0);
                    look -= 32;
                    if (look < 0) break;
                }
                // else retry window
            }
        }
        if (t == 0) s_prefix = prefix;
    }
    __syncthreads();
    const int bpref = s_prefix;

    if (t == 0) {
        g_pre[b] = bpref + total;
        __threadfence();
        *(volatile int*)&g_st[b] = 2;
    }

    const int excl = bpref + incl - v;
    if (i < N_NODES) {
        g_rowptr[i] = excl;
        g_cursor[i] = excl;
    }
    if (b == SCAN_BLOCKS - 1 && t == 255) g_rowptr[N_NODES] = bpref + total;
}

__global__ void k_fill(const void* __restrict__ ei) {
    int e = blockIdx.x * blockDim.x + threadIdx.x;
    if (e < N_EDGES) {
        int is64 = g_is64;
        int row = load_idx(ei, is64, e);
        int col = load_idx(ei, is64, N_EDGES + e);
        if ((unsigned)row < (unsigned)N_NODES && (unsigned)col < (unsigned)N_NODES) {
            int pos = atomicAdd(&g_cursor[col], 1);
            if ((unsigned)pos < (unsigned)N_EDGES) g_esrc[pos] = row;
        }
    }
}

// ================= K-prep/aconv fused: weights + activations -> fp16 swizzled ========
__global__ void k_prep_aconv(const float* __restrict__ x,
                             const float* __restrict__ Wsrc,
                             const float* __restrict__ Wdst,
                             const float* __restrict__ Wself) {
    int idx = blockIdx.x * blockDim.x + threadIdx.x;

    // ---- activations: unit = 8 consecutive k-elements ----
    if (idx < MTILES * 128 * 32) {
        int row = idx >> 5;
        int j   = idx & 31;
        int mt = row >> 7, ri = row & 127;
        int kc = j >> 3;
        int klb = (j & 7) * 16;
        union { __half h[8]; uint4 u4; } H;
        H.u4 = make_uint4(0, 0, 0, 0);
        if (row < N_NODES) {
            const float4* p = (const float4*)(x + (size_t)row * D + j * 8);
            float4 a = p[0], b = p[1];
            float f[8] = {a.x, a.y, a.z, a.w, b.x, b.y, b.z, b.w};
            #pragma unroll
            for (int q = 0; q < 8; q++) H.h[q] = __float2half(f[q]);
        }
        size_t blk = (size_t)(mt * 4 + kc) * 16384;
        uint32_t sw = swz((uint32_t)(ri * 128 + klb));
        *(uint4*)(g_xh + blk + sw) = H.u4;
    }

    // ---- weights: one element per thread for first 3*D*D threads ----
    if (idx < 3 * D * D) {
        int m = idx >> 16;
        int rem = idx & 65535;
        int k = rem >> 8;
        int n = rem & 255;
        const float* W = (m == 0) ? Wsrc : (m == 1) ? Wdst : Wself;
        __half h = __float2half(W[k * D + n]);
        int ntile = n >> 6, r = n & 63;
        int kc = k >> 6, kl = k & 63;
        uint32_t off = swz((uint32_t)(r * 128 + kl * 2));
        size_t blk = (size_t)((m * 4 + ntile) * 4 + kc) * 8192;
        *(__half*)(g_wt + blk + off) = h;
    }
}

// ================= single-pass fp16 mma.sync fused triple GEMM ====
// CTA: M=128, N=64, 3 matrices. 8 warps 4(m) x 2(n). K = 4 chunks of 64.
// stage = A 16K | B 24K (40K); two stages. 2 CTAs/SM target.
#define STAGE 40960
#define SMEM_TOTAL_G (1024 + 2 * STAGE)

__global__ __launch_bounds__(256, 2)
void k_gemm_mma(const float* __restrict__ bsrc,
                const float* __restrict__ bdst,
                const float* __restrict__ bself,
                float* __restrict__ out) {
    extern __shared__ __align__(1024) char smem[];
    const uint32_t sbase = smem_u32(smem);
    const int tid = threadIdx.x;
    const int wid = tid >> 5;
    const int lid = tid & 31;
    const int m0 = blockIdx.y * 128;
    const int n0 = blockIdx.x * 64;
    const int wm = wid & 3;
    const int wn = wid >> 2;

    float* sb = (float*)(smem + 64);   // 192 bias floats
    if (tid < 64)       sb[tid] = bsrc[n0 + tid];
    else if (tid < 128) sb[tid] = bdst[n0 + tid - 64];
    else if (tid < 192) sb[tid] = bself[n0 + tid - 128];

    const int a_row = wm * 32 + (lid & 15);
    const int a_kh  = (lid >> 4) << 4;
    const int b_row = wn * 32 + (lid & 7) + ((lid >> 4) << 3);
    const int b_kh  = ((lid >> 3) & 1) << 4;

    float acc[3][2][4][4];
    #pragma unroll
    for (int m = 0; m < 3; m++)
        #pragma unroll
        for (int i = 0; i < 2; i++)
            #pragma unroll
            for (int j = 0; j < 4; j++)
                #pragma unroll
                for (int q = 0; q < 4; q++) acc[m][i][j][q] = 0.f;

    auto load_stage = [&](int c, int s) {
        uint32_t dstA = sbase + 1024 + s * STAGE;
        const unsigned char* srcA = g_xh + (size_t)(blockIdx.y * 4 + c) * 16384;
        #pragma unroll
        for (int it = 0; it < 4; it++) {
            int u = tid + it * 256;
            CP_ASYNC16(dstA + u * 16, srcA + u * 16);
        }
        uint32_t dstB = dstA + 16384;
        #pragma unroll
        for (int it = 0; it < 6; it++) {
            int t = tid + it * 256;
            int op = t >> 9;
            int w  = t & 511;
            const unsigned char* srcB = g_wt + (size_t)((op * 4 + blockIdx.x) * 4 + c) * 8192 + w * 16;
            CP_ASYNC16(dstB + op * 8192 + w * 16, srcB);
        }
    };

    load_stage(0, 0);
    CP_COMMIT();

    for (int c = 0; c < 4; c++) {
        const int s = c & 1;
        if (c + 1 < 4) {
            load_stage(c + 1, s ^ 1);
            CP_COMMIT();
            CP_WAIT(1);
        } else {
            CP_WAIT(0);
        }
        __syncthreads();

        const uint32_t abase = sbase + 1024 + s * STAGE;
        const uint32_t bbase = abase + 16384;

        #pragma unroll
        for (int kk = 0; kk < 4; kk++) {
            const int kb = kk * 32;

            uint32_t af[2][4];
            #pragma unroll
            for (int mt = 0; mt < 2; mt++) {
                uint32_t off = swz((uint32_t)((a_row + mt * 16) * 128 + kb + a_kh));
                LDSM_X4(af[mt][0], af[mt][1], af[mt][2], af[mt][3], abase + off);
            }

            #pragma unroll
            for (int mat = 0; mat < 3; mat++) {
                uint32_t bf[4][2];
                uint32_t bb = bbase + (uint32_t)mat * 8192;
                #pragma unroll
                for (int np = 0; np < 2; np++) {
                    uint32_t off = swz((uint32_t)((b_row + np * 16) * 128 + kb + b_kh));
                    LDSM_X4(bf[np * 2][0], bf[np * 2][1],
                            bf[np * 2 + 1][0], bf[np * 2 + 1][1],
                            bb + off);
                }
                #pragma unroll
                for (int mt = 0; mt < 2; mt++) {
                    #pragma unroll
                    for (int nt = 0; nt < 4; nt++) {
                        MMA_FP16(acc[mat][mt][nt], af[mt], bf[nt][0], bf[nt][1]);
                    }
                }
            }
        }
        __syncthreads();
    }

    // ---- epilogue: SRC as fp16, OUT0 as f32 ----
    const int qr = lid >> 2;
    const int qc = (lid & 3) * 2;
    #pragma unroll
    for (int mt = 0; mt < 2; mt++) {
        #pragma unroll
        for (int half = 0; half < 2; half++) {
            int row = m0 + wm * 32 + mt * 16 + qr + half * 8;
            if (row >= N_NODES) continue;
            float degf = (float)g_deg[row];
            #pragma unroll
            for (int nt = 0; nt < 4; nt++) {
                int cl = wn * 32 + nt * 8 + qc;
                float s0 = acc[0][mt][nt][half * 2 + 0] + sb[cl + 0];
                float s1 = acc[0][mt][nt][half * 2 + 1] + sb[cl + 1];
                float o0 = acc[2][mt][nt][half * 2 + 0] + sb[128 + cl + 0]
                         - degf * (acc[1][mt][nt][half * 2 + 0] + sb[64 + cl + 0]);
                float o1 = acc[2][mt][nt][half * 2 + 1] + sb[128 + cl + 1]
                         - degf * (acc[1][mt][nt][half * 2 + 1] + sb[64 + cl + 1]);
                *(__half2*)&g_srch[(size_t)row * D + n0 + cl] = __floats2half2_rn(s0, s1);
                *(float2*)&out[(size_t)row * D + n0 + cl]     = make_float2(o0, o1);
            }
        }
    }
}

// ================= K6: warp-per-node gather reduce (fp16 SRC) =================
// lane owns 8 dims via one uint4 (8 x fp16) per neighbor; ids broadcast by shfl.
__global__ __launch_bounds__(256)
void k_reduce(float* __restrict__ out) {
    const int wid  = threadIdx.x >> 5;
    const int lane = threadIdx.x & 31;
    const int v = blockIdx.x * 8 + wid;
    if (v >= N_NODES) return;
    const int s = g_rowptr[v];
    const int e = g_rowptr[v + 1];
    if (e == s) return;

    float acc0 = 0.f, acc1 = 0.f, acc2 = 0.f, acc3 = 0.f;
    float acc4 = 0.f, acc5 = 0.f, acc6 = 0.f, acc7 = 0.f;
    const size_t doff = (size_t)lane * 8;

    for (int j = s; j < e; j += 32) {
        int cnt = min(32, e - j);
        int myn = (lane < cnt) ? g_esrc[j + lane] : 0;
        #pragma unroll 4
        for (int k = 0; k < cnt; k++) {
            int nb = __shfl_sync(0xffffffff, myn, k);
            uint4 u = *(const uint4*)(g_srch + (size_t)nb * D + doff);
            const __half2* h = (const __half2*)&u;
            float2 f0 = __half22float2(h[0]);
            float2 f1 = __half22float2(h[1]);
            float2 f2 = __half22float2(h[2]);
            float2 f3 = __half22float2(h[3]);
            acc0 += f0.x; acc1 += f0.y; acc2 += f1.x; acc3 += f1.y;
            acc4 += f2.x; acc5 += f2.y; acc6 += f3.x; acc7 += f3.y;
        }
    }

    float4* o = (float4*)(out + (size_t)v * D + doff);
    float4 a = o[0], b = o[1];
    a.x += acc0; a.y += acc1; a.z += acc2; a.w += acc3;
    b.x += acc4; b.y += acc5; b.z += acc6; b.w += acc7;
    o[0] = a; o[1] = b;
}

// ================= launch =================
extern "C" void kernel_launch(void* const* d_in, const int* in_sizes, int n_in,
                              void* d_out, int out_size) {
    const float* x     = (const float*)d_in[0];
    const void*  ei    = d_in[1];
    const float* Wsrc  = (const float*)d_in[2];
    const float* bsrc  = (const float*)d_in[3];
    const float* Wdst  = (const float*)d_in[4];
    const float* bdst  = (const float*)d_in[5];
    const float* Wself = (const float*)d_in[6];
    const float* bself = (const float*)d_in[7];
    float* out = (float*)d_out;

    k_zero_deg<<<SCAN_BLOCKS, 256>>>((const int*)ei);
    k_hist<<<(N_EDGES + 255) / 256, 256>>>(ei);
    k_scan<<<SCAN_BLOCKS, 256>>>();
    k_fill<<<(N_EDGES + 255) / 256, 256>>>(ei);
    k_prep_aconv<<<(MTILES * 128 * 32 + 255) / 256, 256>>>(x, Wsrc, Wdst, Wself);

    cudaFuncSetAttribute(k_gemm_mma, cudaFuncAttributeMaxDynamicSharedMemorySize, SMEM_TOTAL_G);
    dim3 ggrid(4, MTILES);                     // (4, 391)
    k_gemm_mma<<<ggrid, 256, SMEM_TOTAL_G>>>(bsrc, bdst, bself, out);

    k_reduce<<<(N_NODES + 7) / 8, 256>>>(out);
}

// round 11
// speedup vs baseline: 4.4223x; 1.0420x over previous
#include <cuda_runtime.h>
#include <cuda_fp16.h>
#include <stdint.h>

#define N_NODES 50000
#define N_EDGES 800000
#define D 256
#define MTILES 391           // ceil(50000/128)
#define SCAN_BLOCKS 196      // ceil(50000/256)

// ================= device scratch (no dynamic allocation allowed) =================
__device__ __half g_srch[(size_t)N_NODES * D]; // SRC = x@W_src + b_src (fp16)
__device__ __half g_dsth[(size_t)N_NODES * D]; // DST = x@W_dst + b_dst (fp16)
__device__ int   g_deg[N_NODES];
__device__ int   g_rowptr[N_NODES + 1];
__device__ int   g_cursor[N_NODES];
__device__ int   g_esrc[N_EDGES];
__device__ int   g_is64;
// decoupled-lookback scan state
__device__ int   g_agg[SCAN_BLOCKS];
__device__ int   g_pre[SCAN_BLOCKS];
__device__ int   g_st[SCAN_BLOCKS];
// pre-transposed, pre-swizzled fp16 weights:
// block id = (mat*4 + ntile)*4 + kchunk, each 8192 B (64n x 64k fp16, SW128)
__device__ __align__(256) unsigned char g_wt[3 * 4 * 4 * 8192];
// pre-converted, pre-swizzled fp16 activations: block id = mtile*4 + kchunk, each 16384 B
__device__ __align__(256) unsigned char g_xh[(size_t)MTILES * 4 * 16384];

__device__ __forceinline__ uint32_t smem_u32(const void* p) {
    uint32_t a;
    asm("{ .reg .u64 t; cvta.to.shared.u64 t, %1; cvt.u32.u64 %0, t; }" : "=r"(a) : "l"(p));
    return a;
}
__device__ __forceinline__ uint32_t swz(uint32_t off) { return off ^ ((off >> 3) & 0x70); }

#define LDSM_X4(r0, r1, r2, r3, addr) \
    asm volatile("ldmatrix.sync.aligned.m8n8.x4.shared.b16 {%0,%1,%2,%3}, [%4];" \
        : "=r"(r0), "=r"(r1), "=r"(r2), "=r"(r3) : "r"(addr))

#define MMA_FP16(c, a, b0v, b1v) \
    asm volatile("mma.sync.aligned.m16n8k16.row.col.f32.f16.f16.f32 " \
        "{%0,%1,%2,%3}, {%4,%5,%6,%7}, {%8,%9}, {%0,%1,%2,%3};" \
        : "+f"((c)[0]), "+f"((c)[1]), "+f"((c)[2]), "+f"((c)[3]) \
        : "r"((a)[0]), "r"((a)[1]), "r"((a)[2]), "r"((a)[3]), "r"(b0v), "r"(b1v))

#define CP_ASYNC16(dst_u32, src_ptr) \
    asm volatile("cp.async.cg.shared.global [%0], [%1], 16;" :: "r"(dst_u32), "l"(src_ptr) : "memory")
#define CP_COMMIT() asm volatile("cp.async.commit_group;" ::: "memory")
#define CP_WAIT(n)  asm volatile("cp.async.wait_group %0;" :: "n"(n) : "memory")

__device__ __forceinline__ int load_idx(const void* ei, int is64, int pos) {
    if (is64) return (int)((const long long*)ei)[pos];
    return ((const int*)ei)[pos];
}

// ================= K1: zero degree + scan state + dtype detect (fused) =================
__global__ void k_zero_deg(const int* __restrict__ ei32) {
    int i = blockIdx.x * blockDim.x + threadIdx.x;
    if (i < N_NODES) g_deg[i] = 0;
    if (i < SCAN_BLOCKS) g_st[i] = 0;
    if (blockIdx.x == 0 && threadIdx.x == 0) {
        int nz = 0;
        #pragma unroll 8
        for (int q = 0; q < 128; q++) nz |= ei32[2 * q + 1];
        g_is64 = (nz == 0) ? 1 : 0;
    }
}
__global__ void k_hist(const void* __restrict__ ei) {
    int e = blockIdx.x * blockDim.x + threadIdx.x;
    if (e < N_EDGES) {
        int col = load_idx(ei, g_is64, N_EDGES + e);
        if ((unsigned)col < (unsigned)N_NODES) atomicAdd(&g_deg[col], 1);
    }
}

// ================= single-pass decoupled-lookback exclusive scan =================
__global__ __launch_bounds__(256)
void k_scan() {
    __shared__ int sh[256];
    __shared__ int s_prefix;
    const int b = blockIdx.x;
    const int t = threadIdx.x;
    const int i = b * 256 + t;
    const int v = (i < N_NODES) ? g_deg[i] : 0;

    sh[t] = v; __syncthreads();
    #pragma unroll
    for (int off = 1; off < 256; off <<= 1) {
        int u = (t >= off) ? sh[t - off] : 0;
        __syncthreads(); sh[t] += u; __syncthreads();
    }
    const int incl = sh[t];
    const int total = sh[255];

    if (t == 0) {
        g_agg[b] = total;
        __threadfence();
        *(volatile int*)&g_st[b] = 1;
    }

    if (t < 32) {
        int prefix = 0;
        if (b > 0) {
            int look = b - 1;
            while (true) {
                int idx = look - t;
                int st = 2, val = 0;
                if (idx >= 0) {
                    st = *(volatile int*)&g_st[idx];
                    if (st == 2)      val = *(volatile int*)&g_pre[idx];
                    else if (st == 1) val = *(volatile int*)&g_agg[idx];
                }
                unsigned done  = __ballot_sync(0xffffffff, st == 2);
                unsigned ready = __ballot_sync(0xffffffff, st >= 1);
                if (done) {
                    int fd = __ffs(done) - 1;
                    unsigned need = (fd > 0) ? ((1u << fd) - 1) : 0;
                    if ((ready & need) == need) {
                        int contrib = (t <= fd) ? val : 0;
                        #pragma unroll
                        for (int o = 16; o > 0; o >>= 1)
                            contrib += __shfl_down_sync(0xffffffff, contrib, o);
                        prefix += __shfl_sync(0xffffffff, contrib, 0);
                        break;
                    }
                } else if (ready == 0xffffffffu && look >= 31) {
                    int contrib = val;
                    #pragma unroll
                    for (int o = 16; o > 0; o >>= 1)
                        contrib += __shfl_down_sync(0xffffffff, contrib, o);
                    prefix += __shfl_sync(0xffffffff, contrib, 0);
                    look -= 32;
                    if (look < 0) break;
                }
            }
        }
        if (t == 0) s_prefix = prefix;
    }
    __syncthreads();
    const int bpref = s_prefix;

    if (t == 0) {
        g_pre[b] = bpref + total;
        __threadfence();
        *(volatile int*)&g_st[b] = 2;
    }

    const int excl = bpref + incl - v;
    if (i < N_NODES) {
        g_rowptr[i] = excl;
        g_cursor[i] = excl;
    }
    if (b == SCAN_BLOCKS - 1 && t == 255) g_rowptr[N_NODES] = bpref + total;
}

__global__ void k_fill(const void* __restrict__ ei) {
    int e = blockIdx.x * blockDim.x + threadIdx.x;
    if (e < N_EDGES) {
        int is64 = g_is64;
        int row = load_idx(ei, is64, e);
        int col = load_idx(ei, is64, N_EDGES + e);
        if ((unsigned)row < (unsigned)N_NODES && (unsigned)col < (unsigned)N_NODES) {
            int pos = atomicAdd(&g_cursor[col], 1);
            if ((unsigned)pos < (unsigned)N_EDGES) g_esrc[pos] = row;
        }
    }
}

// ================= K-prep/aconv fused: weights + activations -> fp16 swizzled ========
__global__ void k_prep_aconv(const float* __restrict__ x,
                             const float* __restrict__ Wsrc,
                             const float* __restrict__ Wdst,
                             const float* __restrict__ Wself) {
    int idx = blockIdx.x * blockDim.x + threadIdx.x;

    if (idx < MTILES * 128 * 32) {
        int row = idx >> 5;
        int j   = idx & 31;
        int mt = row >> 7, ri = row & 127;
        int kc = j >> 3;
        int klb = (j & 7) * 16;
        union { __half h[8]; uint4 u4; } H;
        H.u4 = make_uint4(0, 0, 0, 0);
        if (row < N_NODES) {
            const float4* p = (const float4*)(x + (size_t)row * D + j * 8);
            float4 a = p[0], b = p[1];
            float f[8] = {a.x, a.y, a.z, a.w, b.x, b.y, b.z, b.w};
            #pragma unroll
            for (int q = 0; q < 8; q++) H.h[q] = __float2half(f[q]);
        }
        size_t blk = (size_t)(mt * 4 + kc) * 16384;
        uint32_t sw = swz((uint32_t)(ri * 128 + klb));
        *(uint4*)(g_xh + blk + sw) = H.u4;
    }

    if (idx < 3 * D * D) {
        int m = idx >> 16;
        int rem = idx & 65535;
        int k = rem >> 8;
        int n = rem & 255;
        const float* W = (m == 0) ? Wsrc : (m == 1) ? Wdst : Wself;
        __half h = __float2half(W[k * D + n]);
        int ntile = n >> 6, r = n & 63;
        int kc = k >> 6, kl = k & 63;
        uint32_t off = swz((uint32_t)(r * 128 + kl * 2));
        size_t blk = (size_t)((m * 4 + ntile) * 4 + kc) * 8192;
        *(__half*)(g_wt + blk + off) = h;
    }
}

// ================= single-pass fp16 mma.sync fused triple GEMM ====
// No CSR dependency: writes SRC(fp16), DST(fp16), SELF(f32 -> out).
#define STAGE 40960
#define SMEM_TOTAL_G (1024 + 2 * STAGE)

__global__ __launch_bounds__(256, 2)
void k_gemm_mma(const float* __restrict__ bsrc,
                const float* __restrict__ bdst,
                const float* __restrict__ bself,
                float* __restrict__ out) {
    extern __shared__ __align__(1024) char smem[];
    const uint32_t sbase = smem_u32(smem);
    const int tid = threadIdx.x;
    const int wid = tid >> 5;
    const int lid = tid & 31;
    const int m0 = blockIdx.y * 128;
    const int n0 = blockIdx.x * 64;
    const int wm = wid & 3;
    const int wn = wid >> 2;

    float* sb = (float*)(smem + 64);   // 192 bias floats
    if (tid < 64)       sb[tid] = bsrc[n0 + tid];
    else if (tid < 128) sb[tid] = bdst[n0 + tid - 64];
    else if (tid < 192) sb[tid] = bself[n0 + tid - 128];

    const int a_row = wm * 32 + (lid & 15);
    const int a_kh  = (lid >> 4) << 4;
    const int b_row = wn * 32 + (lid & 7) + ((lid >> 4) << 3);
    const int b_kh  = ((lid >> 3) & 1) << 4;

    float acc[3][2][4][4];
    #pragma unroll
    for (int m = 0; m < 3; m++)
        #pragma unroll
        for (int i = 0; i < 2; i++)
            #pragma unroll
            for (int j = 0; j < 4; j++)
                #pragma unroll
                for (int q = 0; q < 4; q++) acc[m][i][j][q] = 0.f;

    auto load_stage = [&](int c, int s) {
        uint32_t dstA = sbase + 1024 + s * STAGE;
        const unsigned char* srcA = g_xh + (size_t)(blockIdx.y * 4 + c) * 16384;
        #pragma unroll
        for (int it = 0; it < 4; it++) {
            int u = tid + it * 256;
            CP_ASYNC16(dstA + u * 16, srcA + u * 16);
        }
        uint32_t dstB = dstA + 16384;
        #pragma unroll
        for (int it = 0; it < 6; it++) {
            int t = tid + it * 256;
            int op = t >> 9;
            int w  = t & 511;
            const unsigned char* srcB = g_wt + (size_t)((op * 4 + blockIdx.x) * 4 + c) * 8192 + w * 16;
            CP_ASYNC16(dstB + op * 8192 + w * 16, srcB);
        }
    };

    load_stage(0, 0);
    CP_COMMIT();

    for (int c = 0; c < 4; c++) {
        const int s = c & 1;
        if (c + 1 < 4) {
            load_stage(c + 1, s ^ 1);
            CP_COMMIT();
            CP_WAIT(1);
        } else {
            CP_WAIT(0);
        }
        __syncthreads();

        const uint32_t abase = sbase + 1024 + s * STAGE;
        const uint32_t bbase = abase + 16384;

        #pragma unroll
        for (int kk = 0; kk < 4; kk++) {
            const int kb = kk * 32;

            uint32_t af[2][4];
            #pragma unroll
            for (int mt = 0; mt < 2; mt++) {
                uint32_t off = swz((uint32_t)((a_row + mt * 16) * 128 + kb + a_kh));
                LDSM_X4(af[mt][0], af[mt][1], af[mt][2], af[mt][3], abase + off);
            }

            #pragma unroll
            for (int mat = 0; mat < 3; mat++) {
                uint32_t bf[4][2];
                uint32_t bb = bbase + (uint32_t)mat * 8192;
                #pragma unroll
                for (int np = 0; np < 2; np++) {
                    uint32_t off = swz((uint32_t)((b_row + np * 16) * 128 + kb + b_kh));
                    LDSM_X4(bf[np * 2][0], bf[np * 2][1],
                            bf[np * 2 + 1][0], bf[np * 2 + 1][1],
                            bb + off);
                }
                #pragma unroll
                for (int mt = 0; mt < 2; mt++) {
                    #pragma unroll
                    for (int nt = 0; nt < 4; nt++) {
                        MMA_FP16(acc[mat][mt][nt], af[mt], bf[nt][0], bf[nt][1]);
                    }
                }
            }
        }
        __syncthreads();
    }

    // ---- epilogue: SRC fp16, DST fp16, SELF f32 -> out ----
    const int qr = lid >> 2;
    const int qc = (lid & 3) * 2;
    #pragma unroll
    for (int mt = 0; mt < 2; mt++) {
        #pragma unroll
        for (int half = 0; half < 2; half++) {
            int row = m0 + wm * 32 + mt * 16 + qr + half * 8;
            if (row >= N_NODES) continue;
            #pragma unroll
            for (int nt = 0; nt < 4; nt++) {
                int cl = wn * 32 + nt * 8 + qc;
                float s0 = acc[0][mt][nt][half * 2 + 0] + sb[cl + 0];
                float s1 = acc[0][mt][nt][half * 2 + 1] + sb[cl + 1];
                float d0 = acc[1][mt][nt][half * 2 + 0] + sb[64 + cl + 0];
                float d1 = acc[1][mt][nt][half * 2 + 1] + sb[64 + cl + 1];
                float o0 = acc[2][mt][nt][half * 2 + 0] + sb[128 + cl + 0];
                float o1 = acc[2][mt][nt][half * 2 + 1] + sb[128 + cl + 1];
                *(__half2*)&g_srch[(size_t)row * D + n0 + cl] = __floats2half2_rn(s0, s1);
                *(__half2*)&g_dsth[(size_t)row * D + n0 + cl] = __floats2half2_rn(d0, d1);
                *(float2*)&out[(size_t)row * D + n0 + cl]     = make_float2(o0, o1);
            }
        }
    }
}

// ================= K6: warp-per-node gather reduce + deg*dst term =================
__global__ __launch_bounds__(256)
void k_reduce(float* __restrict__ out) {
    const int wid  = threadIdx.x >> 5;
    const int lane = threadIdx.x & 31;
    const int v = blockIdx.x * 8 + wid;
    if (v >= N_NODES) return;
    const int s = g_rowptr[v];
    const int e = g_rowptr[v + 1];
    if (e == s) return;
    const float degf = (float)(e - s);

    float acc0 = 0.f, acc1 = 0.f, acc2 = 0.f, acc3 = 0.f;
    float acc4 = 0.f, acc5 = 0.f, acc6 = 0.f, acc7 = 0.f;
    const size_t doff = (size_t)lane * 8;

    for (int j = s; j < e; j += 32) {
        int cnt = min(32, e - j);
        int myn = (lane < cnt) ? g_esrc[j + lane] : 0;
        #pragma unroll 4
        for (int k = 0; k < cnt; k++) {
            int nb = __shfl_sync(0xffffffff, myn, k);
            uint4 u = *(const uint4*)(g_srch + (size_t)nb * D + doff);
            const __half2* h = (const __half2*)&u;
            float2 f0 = __half22float2(h[0]);
            float2 f1 = __half22float2(h[1]);
            float2 f2 = __half22float2(h[2]);
            float2 f3 = __half22float2(h[3]);
            acc0 += f0.x; acc1 += f0.y; acc2 += f1.x; acc3 += f1.y;
            acc4 += f2.x; acc5 += f2.y; acc6 += f3.x; acc7 += f3.y;
        }
    }

    // subtract deg * dst[v]
    {
        uint4 u = *(const uint4*)(g_dsth + (size_t)v * D + doff);
        const __half2* h = (const __half2*)&u;
        float2 f0 = __half22float2(h[0]);
        float2 f1 = __half22float2(h[1]);
        float2 f2 = __half22float2(h[2]);
        float2 f3 = __half22float2(h[3]);
        acc0 -= degf * f0.x; acc1 -= degf * f0.y;
        acc2 -= degf * f1.x; acc3 -= degf * f1.y;
        acc4 -= degf * f2.x; acc5 -= degf * f2.y;
        acc6 -= degf * f3.x; acc7 -= degf * f3.y;
    }

    float4* o = (float4*)(out + (size_t)v * D + doff);
    float4 a = o[0], b = o[1];
    a.x += acc0; a.y += acc1; a.z += acc2; a.w += acc3;
    b.x += acc4; b.y += acc5; b.z += acc6; b.w += acc7;
    o[0] = a; o[1] = b;
}

// ================= host-side stream/event setup (no device memory) =================
static cudaStream_t g_s2 = 0;
static cudaEvent_t  g_evA = 0, g_evB = 0;
static bool g_streams_ok = false;
namespace {
struct _StreamInit {
    _StreamInit() {
        bool ok = (cudaStreamCreateWithFlags(&g_s2, cudaStreamNonBlocking) == cudaSuccess);
        ok = ok && (cudaEventCreateWithFlags(&g_evA, cudaEventDisableTiming) == cudaSuccess);
        ok = ok && (cudaEventCreateWithFlags(&g_evB, cudaEventDisableTiming) == cudaSuccess);
        g_streams_ok = ok;
    }
};
static _StreamInit _stream_init;
}

// ================= launch =================
extern "C" void kernel_launch(void* const* d_in, const int* in_sizes, int n_in,
                              void* d_out, int out_size) {
    const float* x     = (const float*)d_in[0];
    const void*  ei    = d_in[1];
    const float* Wsrc  = (const float*)d_in[2];
    const float* bsrc  = (const float*)d_in[3];
    const float* Wdst  = (const float*)d_in[4];
    const float* bdst  = (const float*)d_in[5];
    const float* Wself = (const float*)d_in[6];
    const float* bself = (const float*)d_in[7];
    float* out = (float*)d_out;

    cudaFuncSetAttribute(k_gemm_mma, cudaFuncAttributeMaxDynamicSharedMemorySize, SMEM_TOTAL_G);
    dim3 ggrid(4, MTILES);

    if (g_streams_ok) {
        // fork: projection chain on g_s2, CSR chain on capture stream
        cudaEventRecord(g_evA, 0);
        cudaStreamWaitEvent(g_s2, g_evA, 0);

        k_prep_aconv<<<(MTILES * 128 * 32 + 255) / 256, 256, 0, g_s2>>>(x, Wsrc, Wdst, Wself);
        k_gemm_mma<<<ggrid, 256, SMEM_TOTAL_G, g_s2>>>(bsrc, bdst, bself, out);
        cudaEventRecord(g_evB, g_s2);

        k_zero_deg<<<SCAN_BLOCKS, 256>>>((const int*)ei);
        k_hist<<<(N_EDGES + 255) / 256, 256>>>(ei);
        k_scan<<<SCAN_BLOCKS, 256>>>();
        k_fill<<<(N_EDGES + 255) / 256, 256>>>(ei);

        cudaStreamWaitEvent(0, g_evB, 0);   // join
        k_reduce<<<(N_NODES + 7) / 8, 256>>>(out);
    } else {
        k_zero_deg<<<SCAN_BLOCKS, 256>>>((const int*)ei);
        k_hist<<<(N_EDGES + 255) / 256, 256>>>(ei);
        k_scan<<<SCAN_BLOCKS, 256>>>();
        k_fill<<<(N_EDGES + 255) / 256, 256>>>(ei);
        k_prep_aconv<<<(MTILES * 128 * 32 + 255) / 256, 256>>>(x, Wsrc, Wdst, Wself);
        k_gemm_mma<<<ggrid, 256, SMEM_TOTAL_G>>>(bsrc, bdst, bself, out);
        k_reduce<<<(N_NODES + 7) / 8, 256>>>(out);
    }
}

// round 12
// speedup vs baseline: 4.4547x; 1.0073x over previous
#include <cuda_runtime.h>
#include <cuda_fp16.h>
#include <stdint.h>

#define N_NODES 50000
#define N_EDGES 800000
#define D 256
#define MTILES 391           // ceil(50000/128)
#define SCAN_BLOCKS 196      // ceil(50000/256)

// ================= device scratch (no dynamic allocation allowed) =================
__device__ __half g_srch[(size_t)N_NODES * D];  // SRC  = x@W_src  + b_src  (fp16)
__device__ __half g_dsth[(size_t)N_NODES * D];  // DST  = x@W_dst  + b_dst  (fp16)
__device__ __half g_selfh[(size_t)N_NODES * D]; // SELF = x@W_self + b_self (fp16)
__device__ int   g_deg[N_NODES];
__device__ int   g_rowptr[N_NODES + 1];
__device__ int   g_cursor[N_NODES];
__device__ int   g_esrc[N_EDGES];
__device__ int   g_is64;
// decoupled-lookback scan state
__device__ int   g_agg[SCAN_BLOCKS];
__device__ int   g_pre[SCAN_BLOCKS];
__device__ int   g_st[SCAN_BLOCKS];
// pre-transposed, pre-swizzled fp16 weights:
// block id = (mat*4 + ntile)*4 + kchunk, each 8192 B (64n x 64k fp16, SW128)
__device__ __align__(256) unsigned char g_wt[3 * 4 * 4 * 8192];
// pre-converted, pre-swizzled fp16 activations: block id = mtile*4 + kchunk, each 16384 B
__device__ __align__(256) unsigned char g_xh[(size_t)MTILES * 4 * 16384];

__device__ __forceinline__ uint32_t smem_u32(const void* p) {
    uint32_t a;
    asm("{ .reg .u64 t; cvta.to.shared.u64 t, %1; cvt.u32.u64 %0, t; }" : "=r"(a) : "l"(p));
    return a;
}
__device__ __forceinline__ uint32_t swz(uint32_t off) { return off ^ ((off >> 3) & 0x70); }

#define LDSM_X4(r0, r1, r2, r3, addr) \
    asm volatile("ldmatrix.sync.aligned.m8n8.x4.shared.b16 {%0,%1,%2,%3}, [%4];" \
        : "=r"(r0), "=r"(r1), "=r"(r2), "=r"(r3) : "r"(addr))

#define MMA_FP16(c, a, b0v, b1v) \
    asm volatile("mma.sync.aligned.m16n8k16.row.col.f32.f16.f16.f32 " \
        "{%0,%1,%2,%3}, {%4,%5,%6,%7}, {%8,%9}, {%0,%1,%2,%3};" \
        : "+f"((c)[0]), "+f"((c)[1]), "+f"((c)[2]), "+f"((c)[3]) \
        : "r"((a)[0]), "r"((a)[1]), "r"((a)[2]), "r"((a)[3]), "r"(b0v), "r"(b1v))

#define CP_ASYNC16(dst_u32, src_ptr) \
    asm volatile("cp.async.cg.shared.global [%0], [%1], 16;" :: "r"(dst_u32), "l"(src_ptr) : "memory")
#define CP_COMMIT() asm volatile("cp.async.commit_group;" ::: "memory")
#define CP_WAIT(n)  asm volatile("cp.async.wait_group %0;" :: "n"(n) : "memory")

__device__ __forceinline__ int load_idx(const void* ei, int is64, int pos) {
    if (is64) return (int)((const long long*)ei)[pos];
    return ((const int*)ei)[pos];
}

// ================= K1: zero degree + scan state + dtype detect (fused) =================
__global__ void k_zero_deg(const int* __restrict__ ei32) {
    int i = blockIdx.x * blockDim.x + threadIdx.x;
    if (i < N_NODES) g_deg[i] = 0;
    if (i < SCAN_BLOCKS) g_st[i] = 0;
    if (blockIdx.x == 0 && threadIdx.x == 0) {
        int nz = 0;
        #pragma unroll 8
        for (int q = 0; q < 128; q++) nz |= ei32[2 * q + 1];
        g_is64 = (nz == 0) ? 1 : 0;
    }
}
__global__ void k_hist(const void* __restrict__ ei) {
    int e = blockIdx.x * blockDim.x + threadIdx.x;
    if (e < N_EDGES) {
        int col = load_idx(ei, g_is64, N_EDGES + e);
        if ((unsigned)col < (unsigned)N_NODES) atomicAdd(&g_deg[col], 1);
    }
}

// ================= single-pass decoupled-lookback exclusive scan =================
__global__ __launch_bounds__(256)
void k_scan() {
    __shared__ int sh[256];
    __shared__ int s_prefix;
    const int b = blockIdx.x;
    const int t = threadIdx.x;
    const int i = b * 256 + t;
    const int v = (i < N_NODES) ? g_deg[i] : 0;

    sh[t] = v; __syncthreads();
    #pragma unroll
    for (int off = 1; off < 256; off <<= 1) {
        int u = (t >= off) ? sh[t - off] : 0;
        __syncthreads(); sh[t] += u; __syncthreads();
    }
    const int incl = sh[t];
    const int total = sh[255];

    if (t == 0) {
        g_agg[b] = total;
        __threadfence();
        *(volatile int*)&g_st[b] = 1;
    }

    if (t < 32) {
        int prefix = 0;
        if (b > 0) {
            int look = b - 1;
            while (true) {
                int idx = look - t;
                int st = 2, val = 0;
                if (idx >= 0) {
                    st = *(volatile int*)&g_st[idx];
                    if (st == 2)      val = *(volatile int*)&g_pre[idx];
                    else if (st == 1) val = *(volatile int*)&g_agg[idx];
                }
                unsigned done  = __ballot_sync(0xffffffff, st == 2);
                unsigned ready = __ballot_sync(0xffffffff, st >= 1);
                if (done) {
                    int fd = __ffs(done) - 1;
                    unsigned need = (fd > 0) ? ((1u << fd) - 1) : 0;
                    if ((ready & need) == need) {
                        int contrib = (t <= fd) ? val : 0;
                        #pragma unroll
                        for (int o = 16; o > 0; o >>= 1)
                            contrib += __shfl_down_sync(0xffffffff, contrib, o);
                        prefix += __shfl_sync(0xffffffff, contrib, 0);
                        break;
                    }
                } else if (ready == 0xffffffffu && look >= 31) {
                    int contrib = val;
                    #pragma unroll
                    for (int o = 16; o > 0; o >>= 1)
                        contrib += __shfl_down_sync(0xffffffff, contrib, o);
                    prefix += __shfl_sync(0xffffffff, contrib, 0);
                    look -= 32;
                    if (look < 0) break;
                }
            }
        }
        if (t == 0) s_prefix = prefix;
    }
    __syncthreads();
    const int bpref = s_prefix;

    if (t == 0) {
        g_pre[b] = bpref + total;
        __threadfence();
        *(volatile int*)&g_st[b] = 2;
    }

    const int excl = bpref + incl - v;
    if (i < N_NODES) {
        g_rowptr[i] = excl;
        g_cursor[i] = excl;
    }
    if (b == SCAN_BLOCKS - 1 && t == 255) g_rowptr[N_NODES] = bpref + total;
}

__global__ void k_fill(const void* __restrict__ ei) {
    int e = blockIdx.x * blockDim.x + threadIdx.x;
    if (e < N_EDGES) {
        int is64 = g_is64;
        int row = load_idx(ei, is64, e);
        int col = load_idx(ei, is64, N_EDGES + e);
        if ((unsigned)row < (unsigned)N_NODES && (unsigned)col < (unsigned)N_NODES) {
            int pos = atomicAdd(&g_cursor[col], 1);
            if ((unsigned)pos < (unsigned)N_EDGES) g_esrc[pos] = row;
        }
    }
}

// ================= K-prep/aconv fused: weights + activations -> fp16 swizzled ========
__global__ void k_prep_aconv(const float* __restrict__ x,
                             const float* __restrict__ Wsrc,
                             const float* __restrict__ Wdst,
                             const float* __restrict__ Wself) {
    int idx = blockIdx.x * blockDim.x + threadIdx.x;

    if (idx < MTILES * 128 * 32) {
        int row = idx >> 5;
        int j   = idx & 31;
        int mt = row >> 7, ri = row & 127;
        int kc = j >> 3;
        int klb = (j & 7) * 16;
        union { __half h[8]; uint4 u4; } H;
        H.u4 = make_uint4(0, 0, 0, 0);
        if (row < N_NODES) {
            const float4* p = (const float4*)(x + (size_t)row * D + j * 8);
            float4 a = p[0], b = p[1];
            float f[8] = {a.x, a.y, a.z, a.w, b.x, b.y, b.z, b.w};
            #pragma unroll
            for (int q = 0; q < 8; q++) H.h[q] = __float2half(f[q]);
        }
        size_t blk = (size_t)(mt * 4 + kc) * 16384;
        uint32_t sw = swz((uint32_t)(ri * 128 + klb));
        *(uint4*)(g_xh + blk + sw) = H.u4;
    }

    if (idx < 3 * D * D) {
        int m = idx >> 16;
        int rem = idx & 65535;
        int k = rem >> 8;
        int n = rem & 255;
        const float* W = (m == 0) ? Wsrc : (m == 1) ? Wdst : Wself;
        __half h = __float2half(W[k * D + n]);
        int ntile = n >> 6, r = n & 63;
        int kc = k >> 6, kl = k & 63;
        uint32_t off = swz((uint32_t)(r * 128 + kl * 2));
        size_t blk = (size_t)((m * 4 + ntile) * 4 + kc) * 8192;
        *(__half*)(g_wt + blk + off) = h;
    }
}

// ================= single-pass fp16 mma.sync fused triple GEMM ====
// No CSR dependency, no d_out writes: SRC/DST/SELF all fp16 scratch.
#define STAGE 40960
#define SMEM_TOTAL_G (1024 + 2 * STAGE)

__global__ __launch_bounds__(256, 2)
void k_gemm_mma(const float* __restrict__ bsrc,
                const float* __restrict__ bdst,
                const float* __restrict__ bself) {
    extern __shared__ __align__(1024) char smem[];
    const uint32_t sbase = smem_u32(smem);
    const int tid = threadIdx.x;
    const int wid = tid >> 5;
    const int lid = tid & 31;
    const int m0 = blockIdx.y * 128;
    const int n0 = blockIdx.x * 64;
    const int wm = wid & 3;
    const int wn = wid >> 2;

    float* sb = (float*)(smem + 64);   // 192 bias floats
    if (tid < 64)       sb[tid] = bsrc[n0 + tid];
    else if (tid < 128) sb[tid] = bdst[n0 + tid - 64];
    else if (tid < 192) sb[tid] = bself[n0 + tid - 128];

    const int a_row = wm * 32 + (lid & 15);
    const int a_kh  = (lid >> 4) << 4;
    const int b_row = wn * 32 + (lid & 7) + ((lid >> 4) << 3);
    const int b_kh  = ((lid >> 3) & 1) << 4;

    float acc[3][2][4][4];
    #pragma unroll
    for (int m = 0; m < 3; m++)
        #pragma unroll
        for (int i = 0; i < 2; i++)
            #pragma unroll
            for (int j = 0; j < 4; j++)
                #pragma unroll
                for (int q = 0; q < 4; q++) acc[m][i][j][q] = 0.f;

    auto load_stage = [&](int c, int s) {
        uint32_t dstA = sbase + 1024 + s * STAGE;
        const unsigned char* srcA = g_xh + (size_t)(blockIdx.y * 4 + c) * 16384;
        #pragma unroll
        for (int it = 0; it < 4; it++) {
            int u = tid + it * 256;
            CP_ASYNC16(dstA + u * 16, srcA + u * 16);
        }
        uint32_t dstB = dstA + 16384;
        #pragma unroll
        for (int it = 0; it < 6; it++) {
            int t = tid + it * 256;
            int op = t >> 9;
            int w  = t & 511;
            const unsigned char* srcB = g_wt + (size_t)((op * 4 + blockIdx.x) * 4 + c) * 8192 + w * 16;
            CP_ASYNC16(dstB + op * 8192 + w * 16, srcB);
        }
    };

    load_stage(0, 0);
    CP_COMMIT();

    for (int c = 0; c < 4; c++) {
        const int s = c & 1;
        if (c + 1 < 4) {
            load_stage(c + 1, s ^ 1);
            CP_COMMIT();
            CP_WAIT(1);
        } else {
            CP_WAIT(0);
        }
        __syncthreads();

        const uint32_t abase = sbase + 1024 + s * STAGE;
        const uint32_t bbase = abase + 16384;

        #pragma unroll
        for (int kk = 0; kk < 4; kk++) {
            const int kb = kk * 32;

            uint32_t af[2][4];
            #pragma unroll
            for (int mt = 0; mt < 2; mt++) {
                uint32_t off = swz((uint32_t)((a_row + mt * 16) * 128 + kb + a_kh));
                LDSM_X4(af[mt][0], af[mt][1], af[mt][2], af[mt][3], abase + off);
            }

            #pragma unroll
            for (int mat = 0; mat < 3; mat++) {
                uint32_t bf[4][2];
                uint32_t bb = bbase + (uint32_t)mat * 8192;
                #pragma unroll
                for (int np = 0; np < 2; np++) {
                    uint32_t off = swz((uint32_t)((b_row + np * 16) * 128 + kb + b_kh));
                    LDSM_X4(bf[np * 2][0], bf[np * 2][1],
                            bf[np * 2 + 1][0], bf[np * 2 + 1][1],
                            bb + off);
                }
                #pragma unroll
                for (int mt = 0; mt < 2; mt++) {
                    #pragma unroll
                    for (int nt = 0; nt < 4; nt++) {
                        MMA_FP16(acc[mat][mt][nt], af[mt], bf[nt][0], bf[nt][1]);
                    }
                }
            }
        }
        __syncthreads();
    }

    // ---- epilogue: SRC/DST/SELF all fp16 ----
    const int qr = lid >> 2;
    const int qc = (lid & 3) * 2;
    #pragma unroll
    for (int mt = 0; mt < 2; mt++) {
        #pragma unroll
        for (int half = 0; half < 2; half++) {
            int row = m0 + wm * 32 + mt * 16 + qr + half * 8;
            if (row >= N_NODES) continue;
            #pragma unroll
            for (int nt = 0; nt < 4; nt++) {
                int cl = wn * 32 + nt * 8 + qc;
                float s0 = acc[0][mt][nt][half * 2 + 0] + sb[cl + 0];
                float s1 = acc[0][mt][nt][half * 2 + 1] + sb[cl + 1];
                float d0 = acc[1][mt][nt][half * 2 + 0] + sb[64 + cl + 0];
                float d1 = acc[1][mt][nt][half * 2 + 1] + sb[64 + cl + 1];
                float o0 = acc[2][mt][nt][half * 2 + 0] + sb[128 + cl + 0];
                float o1 = acc[2][mt][nt][half * 2 + 1] + sb[128 + cl + 1];
                *(__half2*)&g_srch[(size_t)row * D + n0 + cl]  = __floats2half2_rn(s0, s1);
                *(__half2*)&g_dsth[(size_t)row * D + n0 + cl]  = __floats2half2_rn(d0, d1);
                *(__half2*)&g_selfh[(size_t)row * D + n0 + cl] = __floats2half2_rn(o0, o1);
            }
        }
    }
}

// ================= K6: warp-per-node reduce, write-only out =================
// out[v] = selfh[v] + sum_{nbr} srch[nbr] - deg(v) * dsth[v]
__global__ __launch_bounds__(256)
void k_reduce(float* __restrict__ out) {
    const int wid  = threadIdx.x >> 5;
    const int lane = threadIdx.x & 31;
    const int v = blockIdx.x * 8 + wid;
    if (v >= N_NODES) return;
    const int s = g_rowptr[v];
    const int e = g_rowptr[v + 1];
    const float degf = (float)(e - s);

    float acc0 = 0.f, acc1 = 0.f, acc2 = 0.f, acc3 = 0.f;
    float acc4 = 0.f, acc5 = 0.f, acc6 = 0.f, acc7 = 0.f;
    const size_t doff = (size_t)lane * 8;

    for (int j = s; j < e; j += 32) {
        int cnt = min(32, e - j);
        int myn = (lane < cnt) ? g_esrc[j + lane] : 0;
        #pragma unroll 4
        for (int k = 0; k < cnt; k++) {
            int nb = __shfl_sync(0xffffffff, myn, k);
            uint4 u = *(const uint4*)(g_srch + (size_t)nb * D + doff);
            const __half2* h = (const __half2*)&u;
            float2 f0 = __half22float2(h[0]);
            float2 f1 = __half22float2(h[1]);
            float2 f2 = __half22float2(h[2]);
            float2 f3 = __half22float2(h[3]);
            acc0 += f0.x; acc1 += f0.y; acc2 += f1.x; acc3 += f1.y;
            acc4 += f2.x; acc5 += f2.y; acc6 += f3.x; acc7 += f3.y;
        }
    }

    // + self - deg * dst
    {
        uint4 us = *(const uint4*)(g_selfh + (size_t)v * D + doff);
        uint4 ud = *(const uint4*)(g_dsth  + (size_t)v * D + doff);
        const __half2* hs = (const __half2*)&us;
        const __half2* hd = (const __half2*)&ud;
        float2 s0 = __half22float2(hs[0]), d0 = __half22float2(hd[0]);
        float2 s1 = __half22float2(hs[1]), d1 = __half22float2(hd[1]);
        float2 s2 = __half22float2(hs[2]), d2 = __half22float2(hd[2]);
        float2 s3 = __half22float2(hs[3]), d3 = __half22float2(hd[3]);
        acc0 += s0.x - degf * d0.x; acc1 += s0.y - degf * d0.y;
        acc2 += s1.x - degf * d1.x; acc3 += s1.y - degf * d1.y;
        acc4 += s2.x - degf * d2.x; acc5 += s2.y - degf * d2.y;
        acc6 += s3.x - degf * d3.x; acc7 += s3.y - degf * d3.y;
    }

    float4* o = (float4*)(out + (size_t)v * D + doff);
    o[0] = make_float4(acc0, acc1, acc2, acc3);
    o[1] = make_float4(acc4, acc5, acc6, acc7);
}

// ================= host-side stream/event setup (no device memory) =================
static cudaStream_t g_s2 = 0;
static cudaEvent_t  g_evA = 0, g_evB = 0;
static bool g_streams_ok = false;
namespace {
struct _StreamInit {
    _StreamInit() {
        bool ok = (cudaStreamCreateWithFlags(&g_s2, cudaStreamNonBlocking) == cudaSuccess);
        ok = ok && (cudaEventCreateWithFlags(&g_evA, cudaEventDisableTiming) == cudaSuccess);
        ok = ok && (cudaEventCreateWithFlags(&g_evB, cudaEventDisableTiming) == cudaSuccess);
        g_streams_ok = ok;
    }
};
static _StreamInit _stream_init;
}

// ================= launch =================
extern "C" void kernel_launch(void* const* d_in, const int* in_sizes, int n_in,
                              void* d_out, int out_size) {
    const float* x     = (const float*)d_in[0];
    const void*  ei    = d_in[1];
    const float* Wsrc  = (const float*)d_in[2];
    const float* bsrc  = (const float*)d_in[3];
    const float* Wdst  = (const float*)d_in[4];
    const float* bdst  = (const float*)d_in[5];
    const float* Wself = (const float*)d_in[6];
    const float* bself = (const float*)d_in[7];
    float* out = (float*)d_out;

    cudaFuncSetAttribute(k_gemm_mma, cudaFuncAttributeMaxDynamicSharedMemorySize, SMEM_TOTAL_G);
    dim3 ggrid(4, MTILES);

    if (g_streams_ok) {
        cudaEventRecord(g_evA, 0);
        cudaStreamWaitEvent(g_s2, g_evA, 0);

        k_prep_aconv<<<(MTILES * 128 * 32 + 255) / 256, 256, 0, g_s2>>>(x, Wsrc, Wdst, Wself);
        k_gemm_mma<<<ggrid, 256, SMEM_TOTAL_G, g_s2>>>(bsrc, bdst, bself);
        cudaEventRecord(g_evB, g_s2);

        k_zero_deg<<<SCAN_BLOCKS, 256>>>((const int*)ei);
        k_hist<<<(N_EDGES + 255) / 256, 256>>>(ei);
        k_scan<<<SCAN_BLOCKS, 256>>>();
        k_fill<<<(N_EDGES + 255) / 256, 256>>>(ei);

        cudaStreamWaitEvent(0, g_evB, 0);
        k_reduce<<<(N_NODES + 7) / 8, 256>>>(out);
    } else {
        k_zero_deg<<<SCAN_BLOCKS, 256>>>((const int*)ei);
        k_hist<<<(N_EDGES + 255) / 256, 256>>>(ei);
        k_scan<<<SCAN_BLOCKS, 256>>>();
        k_fill<<<(N_EDGES + 255) / 256, 256>>>(ei);
        k_prep_aconv<<<(MTILES * 128 * 32 + 255) / 256, 256>>>(x, Wsrc, Wdst, Wself);
        k_gemm_mma<<<ggrid, 256, SMEM_TOTAL_G>>>(bsrc, bdst, bself);
        k_reduce<<<(N_NODES + 7) / 8, 256>>>(out);
    }
}